// round 1
// baseline (speedup 1.0000x reference)
#include <cuda_runtime.h>
#include <math.h>

#define BATCH 2048
#define TTL   30
#define IN_DIM 60
#define HDIM  512
#define G4    2048   // 4*HDIM
#define NL    5
#define OUTD  23
#define TPTS  90

// ---------------- static scratch (no allocs allowed) ----------------
__device__ float g_x30 [BATCH * TTL];        // x / population, layer-0 input
__device__ float g_gate[BATCH * G4];         // LSTM pre-activations
__device__ float g_x   [BATCH * HDIM];       // layer output (ts_out at the end)
__device__ float g_m1  [BATCH * HDIM];       // meta hidden 1
__device__ float g_m2  [BATCH * HDIM];       // meta hidden 2
__device__ float g_z   [BATCH * 2 * HDIM];   // readout hidden

// ---------------- GEMM: C = A1@W1^T + A2@W2^T + b1 + b2, op epilogue ------
// A row-major MxK (stride lda), W row-major NxK (stride ldb).  M,N multiples of 128.
#define BM 128
#define BN 128
#define BK 16

__global__ __launch_bounds__(256)
void gemm_tn(const float* __restrict__ A1, int lda1, const float* __restrict__ W1, int ldb1, int K1,
             const float* __restrict__ A2, int lda2, const float* __restrict__ W2, int ldb2, int K2,
             const float* __restrict__ bias1, const float* __restrict__ bias2,
             float* __restrict__ C, int ldc, int op)
{
    __shared__ __align__(16) float As[BK][BM + 4];
    __shared__ __align__(16) float Bs[BK][BN + 4];

    const int tid = threadIdx.x;
    const int tx  = tid & 15;   // n direction
    const int ty  = tid >> 4;   // m direction
    const int m0  = ty * 8;
    const int n0  = tx * 8;
    const int blockM = blockIdx.y * BM;
    const int blockN = blockIdx.x * BN;

    float acc[8][8];
#pragma unroll
    for (int i = 0; i < 8; i++)
#pragma unroll
        for (int j = 0; j < 8; j++) acc[i][j] = 0.f;

    for (int part = 0; part < 2; part++) {
        const float* A  = part ? A2 : A1;
        const float* W  = part ? W2 : W1;
        const int    lda = part ? lda2 : lda1;
        const int    ldb = part ? ldb2 : ldb1;
        const int    K   = part ? K2 : K1;
        if (K == 0 || A == nullptr) continue;
        const int ktiles = (K + BK - 1) / BK;
        for (int kt = 0; kt < ktiles; kt++) {
            const int k0 = kt * BK;
#pragma unroll
            for (int i = 0; i < 8; i++) {
                int e  = tid + i * 256;
                int r  = e >> 4;
                int kk = e & 15;
                int k  = k0 + kk;
                As[kk][r] = (k < K) ? A[(size_t)(blockM + r) * lda + k] : 0.f;
            }
#pragma unroll
            for (int i = 0; i < 8; i++) {
                int e  = tid + i * 256;
                int r  = e >> 4;
                int kk = e & 15;
                int k  = k0 + kk;
                Bs[kk][r] = (k < K) ? W[(size_t)(blockN + r) * ldb + k] : 0.f;
            }
            __syncthreads();
#pragma unroll
            for (int kk = 0; kk < BK; kk++) {
                float4 a0 = *reinterpret_cast<const float4*>(&As[kk][m0]);
                float4 a1 = *reinterpret_cast<const float4*>(&As[kk][m0 + 4]);
                float4 b0 = *reinterpret_cast<const float4*>(&Bs[kk][n0]);
                float4 b1 = *reinterpret_cast<const float4*>(&Bs[kk][n0 + 4]);
                float av[8] = {a0.x, a0.y, a0.z, a0.w, a1.x, a1.y, a1.z, a1.w};
                float bv[8] = {b0.x, b0.y, b0.z, b0.w, b1.x, b1.y, b1.z, b1.w};
#pragma unroll
                for (int i = 0; i < 8; i++)
#pragma unroll
                    for (int j = 0; j < 8; j++)
                        acc[i][j] += av[i] * bv[j];
            }
            __syncthreads();
        }
    }

#pragma unroll
    for (int j = 0; j < 8; j++) {
        int n = blockN + n0 + j;
        float bb = (bias1 ? bias1[n] : 0.f) + (bias2 ? bias2[n] : 0.f);
#pragma unroll
        for (int i = 0; i < 8; i++) {
            float v = acc[i][j] + bb;
            if (op == 1)      v = fmaxf(v, 0.f);
            else if (op == 2) v = tanhf(v);
            C[(size_t)(blockM + m0 + i) * ldc + n] = v;
        }
    }
}

// ---------------- small kernels ----------------
__global__ void prep_x30(const float* __restrict__ mi, const float* __restrict__ pop,
                         float* __restrict__ x30)
{
    int idx = blockIdx.x * blockDim.x + threadIdx.x;
    if (idx >= BATCH * TTL) return;
    int b = idx / TTL;
    int c = idx - b * TTL;
    x30[idx] = mi[b * IN_DIM + c] / pop[b];
}

__global__ void lstm_cell(const float* __restrict__ g, const float* __restrict__ c0,
                          float* __restrict__ xout, float* __restrict__ ts_out)
{
    int idx = blockIdx.x * blockDim.x + threadIdx.x;
    if (idx >= BATCH * HDIM) return;
    int b = idx >> 9;
    int h = idx & 511;
    const float* gr = g + (size_t)b * G4;
    float gi = gr[h];
    float gf = gr[HDIM + h];
    float gg = gr[2 * HDIM + h];
    float go = gr[3 * HDIM + h];
    float si = 1.f / (1.f + expf(-gi));
    float sf = 1.f / (1.f + expf(-gf));
    float so = 1.f / (1.f + expf(-go));
    float c  = sf * c0[idx] + si * tanhf(gg);
    float xv = so * tanhf(c);
    xout[idx] = xv;
    if (ts_out) ts_out[idx] = xv;
}

// raw = z @ ro_W2^T + ro_b2 ; dnn = sigmoid(raw*scale)*range
__global__ void raw_dnn_kernel(const float* __restrict__ z, const float* __restrict__ W2,
                               const float* __restrict__ b2, const float* __restrict__ rng,
                               const void* __restrict__ scale_ptr,
                               float* __restrict__ raw_out, float* __restrict__ dnn_out)
{
    __shared__ float zs[2 * HDIM];
    int b = blockIdx.x;
    const float* zr = z + (size_t)b * 2 * HDIM;
    for (int i = threadIdx.x; i < 2 * HDIM; i += blockDim.x) zs[i] = zr[i];
    __syncthreads();

    int warp = threadIdx.x >> 5;
    int lane = threadIdx.x & 31;

    // decode sigmoid_scale: works for int32(1), int64(1) low word, or float(1.0)
    int bits = *(const int*)scale_ptr;
    float f  = __int_as_float(bits);
    float af = fabsf(f);
    float s  = (af >= 1e-30f && af <= 1e30f) ? f : (float)bits;

    for (int o = warp; o < OUTD; o += 8) {
        const float* w = W2 + (size_t)o * 2 * HDIM;
        float acc = 0.f;
        for (int k = lane; k < 2 * HDIM; k += 32) acc += zs[k] * w[k];
#pragma unroll
        for (int off = 16; off; off >>= 1) acc += __shfl_xor_sync(0xffffffffu, acc, off);
        if (lane == 0) {
            float r = acc + b2[o];
            raw_out[(size_t)b * OUTD + o] = r;
            dnn_out[(size_t)b * OUTD + o] = (1.f / (1.f + expf(-r * s))) * rng[o];
        }
    }
}

// ---------------- ODE ----------------
#define LN2D 0.6931471805599453
#define C_RI  ((float)(LN2D / 5.0))
#define C_RD  ((float)(LN2D / 2.0))
#define C_RRI ((float)(LN2D / 10.0))
#define C_RRH ((float)(LN2D / 15.0))
#define C_RRV ((float)(LN2D / 10.0))
#define TWO_OVER_PI 0.6366197723675814f
#define HALF_PI     1.5707963267948966f

__device__ __forceinline__ void covid_deriv(const float y[16], float gam, float pdt,
                                            float aN, float r_dth, float d[16])
{
    float S = y[0], E = y[1], I = y[2];
    float AR = y[3], DHR = y[4], DQR = y[5], AD = y[6], DHD = y[7], DQD = y[8];
    float DVR = y[12], DVD = y[13];
    float inf = aN * gam * S * I;
    float det = C_RD * I;
    float d1m = det * (1.f - pdt);
    float dp  = det * pdt;
    d[0]  = -inf;
    d[1]  = inf - C_RI * E;
    d[2]  = C_RI * E - det;
    d[3]  = d1m * (1.0f - 0.2f) - C_RRI * AR;
    d[4]  = d1m * (0.2f * 0.15f) - C_RRH * DHR;
    d[5]  = d1m * (0.2f * (1.0f - 0.15f)) - C_RRI * DQR;
    d[6]  = dp * (1.0f - 0.2f) - r_dth * AD;
    d[7]  = dp * (0.2f * 0.15f) - r_dth * DHD;
    d[8]  = dp * (0.2f * (1.0f - 0.15f)) - r_dth * DQD;
    d[9]  = C_RRI * (AR + DQR) + C_RRH * DHR;
    d[10] = r_dth * (AD + DQD + DHD);
    d[11] = det * (0.2f * 0.15f);
    d[12] = d1m * (0.2f * 0.15f * 0.25f) - C_RRV * DVR;
    d[13] = dp * (0.2f * 0.15f * 0.25f) - r_dth * DVD;
    d[14] = r_dth * (DHD + DQD);
    d[15] = det * 0.2f;
}

__device__ __forceinline__ float gam_f(float t, float days, float rs20,
                                       float jump, float t_jump, float inv2s2)
{
    float a   = atanf((days - t) * rs20);
    float dtj = t - t_jump;
    return TWO_OVER_PI * a + 1.0f + jump * __expf(-dtj * dtj * inv2s2);
}

__device__ __forceinline__ float pdt_f(float t, float pc, float rdd20)
{
    return pc * (atanf(-t * rdd20) + HALF_PI) + 0.001f;
}

__global__ void ode_kernel(const float* __restrict__ pop, const float* __restrict__ ccn,
                           const float* __restrict__ mort, const float* __restrict__ dnn,
                           float* __restrict__ sol)
{
    int b = blockIdx.x * blockDim.x + threadIdx.x;
    if (b >= BATCH) return;
    const float* dn = dnn + (size_t)b * OUTD;
    float alpha = dn[11], days = dn[12], r_s = dn[13], r_dth = dn[14], p_dth = dn[15];
    float r_dthdecay = dn[16], k1 = dn[17], k2 = dn[18], jump = dn[19];
    float t_jump = dn[20], stdn = dn[21];

    float N    = pop[b];
    float PopI = ccn[b];
    float PopD = floorf(mort[b] * PopI);
    float R0   = (PopI - PopD > 5.0f * PopD) ? 5.0f * PopD : 0.0f;
    float PopCI = PopI - PopD - R0;
    float ciPD  = PopCI / 0.2f;
    float omp   = 1.0f - p_dth;

    float y[16];
    y[0]  = N - ciPD * (k1 + k2) - R0 / 0.2f - PopD / 0.2f;
    y[1]  = ciPD * k1;
    y[2]  = ciPD * k2;
    y[3]  = (ciPD - PopCI) * omp;
    y[4]  = PopCI * 0.15f * omp;
    y[5]  = PopCI * (1.0f - 0.15f) * omp;
    y[6]  = (ciPD - PopCI) * p_dth;
    y[7]  = PopCI * 0.15f * p_dth;
    y[8]  = PopCI * (1.0f - 0.15f) * p_dth;
    y[9]  = R0 / 0.2f;
    y[10] = PopD / 0.2f;
    y[11] = PopCI * 0.15f;
    y[12] = PopCI * 0.15f * 0.25f * omp;
    y[13] = PopCI * 0.15f * 0.25f * p_dth;
    y[14] = PopD;
    y[15] = PopI;

    float* srow = sol + (size_t)b * TPTS * 16;
#pragma unroll
    for (int i = 0; i < 16; i++) srow[i] = y[i];

    float aN     = alpha / N;
    float rs20   = r_s * (1.0f / 20.0f);
    float rdd20  = r_dthdecay * (1.0f / 20.0f);
    float inv2s2 = 1.0f / (2.0f * stdn * stdn);
    float pc     = TWO_OVER_PI * (p_dth - 0.001f);
    const float dt = 0.1f;

    for (int seg = 0; seg < TPTS - 1; seg++) {
        float t0 = (float)seg;
        for (int j = 0; j < 10; j++) {
            float t  = t0 + (float)j * dt;
            float tm = t + 0.05f;
            float tp = t + 0.1f;
            // gam/pdt depend only on t: 3 distinct times per substep (k2,k3 share)
            float g1 = gam_f(t,  days, rs20, jump, t_jump, inv2s2);
            float g2 = gam_f(tm, days, rs20, jump, t_jump, inv2s2);
            float g3 = gam_f(tp, days, rs20, jump, t_jump, inv2s2);
            float p1 = pdt_f(t,  pc, rdd20);
            float p2 = pdt_f(tm, pc, rdd20);
            float p3 = pdt_f(tp, pc, rdd20);

            float k[16], acc[16], yy[16];
            covid_deriv(y, g1, p1, aN, r_dth, k);
#pragma unroll
            for (int i = 0; i < 16; i++) { acc[i] = k[i]; yy[i] = y[i] + 0.05f * k[i]; }
            covid_deriv(yy, g2, p2, aN, r_dth, k);
#pragma unroll
            for (int i = 0; i < 16; i++) { acc[i] += 2.f * k[i]; yy[i] = y[i] + 0.05f * k[i]; }
            covid_deriv(yy, g2, p2, aN, r_dth, k);
#pragma unroll
            for (int i = 0; i < 16; i++) { acc[i] += 2.f * k[i]; yy[i] = y[i] + 0.1f * k[i]; }
            covid_deriv(yy, g3, p3, aN, r_dth, k);
#pragma unroll
            for (int i = 0; i < 16; i++) y[i] += (0.1f / 6.0f) * (acc[i] + k[i]);
        }
        float* o = srow + (size_t)(seg + 1) * 16;
#pragma unroll
        for (int i = 0; i < 16; i++) o[i] = y[i];
    }
}

// ---------------- launch ----------------
extern "C" void kernel_launch(void* const* d_in, const int* in_sizes, int n_in,
                              void* d_out, int out_size)
{
    const float* mi   = (const float*)d_in[0];
    const float* pop  = (const float*)d_in[1];
    const float* ccn  = (const float*)d_in[2];
    const float* mort = (const float*)d_in[3];
    const float* h0   = (const float*)d_in[4];
    const float* c0   = (const float*)d_in[5];
    const float* W_ih0= (const float*)d_in[6];
    const float* W_ihR= (const float*)d_in[7];
    const float* W_hh = (const float*)d_in[8];
    const float* b_ih = (const float*)d_in[9];
    const float* b_hh = (const float*)d_in[10];
    const float* mW1  = (const float*)d_in[11];
    const float* mb1  = (const float*)d_in[12];
    const float* mW2  = (const float*)d_in[13];
    const float* mb2  = (const float*)d_in[14];
    const float* rW1  = (const float*)d_in[15];
    const float* rb1  = (const float*)d_in[16];
    const float* rW2  = (const float*)d_in[17];
    const float* rb2  = (const float*)d_in[18];
    const float* rng  = (const float*)d_in[19];
    const void*  scl  = d_in[20];

    float* out  = (float*)d_out;
    float* sol  = out;                                   // (B, 90, 16)
    float* dnn  = out + (size_t)BATCH * TPTS * 16;       // (B, 23)
    float* ts   = dnn + (size_t)BATCH * OUTD;            // (B, 1, 512)
    float* raw  = ts  + (size_t)BATCH * HDIM;            // (B, 23)

    float *x30, *gate, *xb, *m1, *m2, *zb;
    cudaGetSymbolAddress((void**)&x30,  g_x30);
    cudaGetSymbolAddress((void**)&gate, g_gate);
    cudaGetSymbolAddress((void**)&xb,   g_x);
    cudaGetSymbolAddress((void**)&m1,   g_m1);
    cudaGetSymbolAddress((void**)&m2,   g_m2);
    cudaGetSymbolAddress((void**)&zb,   g_z);

    prep_x30<<<(BATCH * TTL + 255) / 256, 256>>>(mi, pop, x30);

    dim3 gGrid(G4 / BN, BATCH / BM);
    for (int l = 0; l < NL; l++) {
        const float* A1 = l ? xb : x30;
        int          K1 = l ? HDIM : TTL;
        const float* W1 = l ? (W_ihR + (size_t)(l - 1) * G4 * HDIM) : W_ih0;
        gemm_tn<<<gGrid, 256>>>(A1, K1, W1, K1, K1,
                                h0 + (size_t)l * BATCH * HDIM, HDIM,
                                W_hh + (size_t)l * G4 * HDIM, HDIM, HDIM,
                                b_ih + (size_t)l * G4, b_hh + (size_t)l * G4,
                                gate, G4, 0);
        lstm_cell<<<(BATCH * HDIM + 255) / 256, 256>>>(
            gate, c0 + (size_t)l * BATCH * HDIM, xb,
            (l == NL - 1) ? ts : nullptr);
    }

    dim3 mGrid(HDIM / BN, BATCH / BM);
    gemm_tn<<<mGrid, 256>>>(mi + TTL, IN_DIM, mW1, TTL, TTL,
                            nullptr, 0, nullptr, 0, 0,
                            mb1, nullptr, m1, HDIM, 1);
    gemm_tn<<<mGrid, 256>>>(m1, HDIM, mW2, HDIM, HDIM,
                            nullptr, 0, nullptr, 0, 0,
                            mb2, nullptr, m2, HDIM, 1);

    dim3 zGrid(2 * HDIM / BN, BATCH / BM);
    gemm_tn<<<zGrid, 256>>>(xb, HDIM, rW1, 2 * HDIM, HDIM,
                            m2, HDIM, rW1 + HDIM, 2 * HDIM, HDIM,
                            rb1, nullptr, zb, 2 * HDIM, 2);

    raw_dnn_kernel<<<BATCH, 256>>>(zb, rW2, rb2, rng, scl, raw, dnn);

    ode_kernel<<<(BATCH + 63) / 64, 64>>>(pop, ccn, mort, dnn, sol);
}

// round 2
// speedup vs baseline: 1.0003x; 1.0003x over previous
#include <cuda_runtime.h>
#include <math.h>

#define BATCH 2048
#define TTL   30
#define IN_DIM 60
#define HDIM  512
#define G4    2048   // 4*HDIM
#define NL    5
#define OUTD  23
#define TPTS  90

// ---------------- static scratch (no allocs allowed) ----------------
__device__ float g_x30 [BATCH * TTL];        // x / population, layer-0 input
__device__ float g_gate[BATCH * G4];         // LSTM pre-activations
__device__ float g_x   [BATCH * HDIM];       // layer output (ts_out at the end)
__device__ float g_m1  [BATCH * HDIM];       // meta hidden 1
__device__ float g_m2  [BATCH * HDIM];       // meta hidden 2
__device__ float g_z   [BATCH * 2 * HDIM];   // readout hidden

// ---------------- GEMM: C = A1@W1^T + A2@W2^T + b1 + b2, op epilogue ------
// A row-major MxK (stride lda), W row-major NxK (stride ldb).  M,N multiples of 128.
#define BM 128
#define BN 128
#define BK 16

__global__ __launch_bounds__(256)
void gemm_tn(const float* __restrict__ A1, int lda1, const float* __restrict__ W1, int ldb1, int K1,
             const float* __restrict__ A2, int lda2, const float* __restrict__ W2, int ldb2, int K2,
             const float* __restrict__ bias1, const float* __restrict__ bias2,
             float* __restrict__ C, int ldc, int op)
{
    __shared__ __align__(16) float As[BK][BM + 4];
    __shared__ __align__(16) float Bs[BK][BN + 4];

    const int tid = threadIdx.x;
    const int tx  = tid & 15;   // n direction
    const int ty  = tid >> 4;   // m direction
    const int m0  = ty * 8;
    const int n0  = tx * 8;
    const int blockM = blockIdx.y * BM;
    const int blockN = blockIdx.x * BN;

    float acc[8][8];
#pragma unroll
    for (int i = 0; i < 8; i++)
#pragma unroll
        for (int j = 0; j < 8; j++) acc[i][j] = 0.f;

    for (int part = 0; part < 2; part++) {
        const float* A  = part ? A2 : A1;
        const float* W  = part ? W2 : W1;
        const int    lda = part ? lda2 : lda1;
        const int    ldb = part ? ldb2 : ldb1;
        const int    K   = part ? K2 : K1;
        if (K == 0 || A == nullptr) continue;
        const int ktiles = (K + BK - 1) / BK;
        for (int kt = 0; kt < ktiles; kt++) {
            const int k0 = kt * BK;
#pragma unroll
            for (int i = 0; i < 8; i++) {
                int e  = tid + i * 256;
                int r  = e >> 4;
                int kk = e & 15;
                int k  = k0 + kk;
                As[kk][r] = (k < K) ? A[(size_t)(blockM + r) * lda + k] : 0.f;
            }
#pragma unroll
            for (int i = 0; i < 8; i++) {
                int e  = tid + i * 256;
                int r  = e >> 4;
                int kk = e & 15;
                int k  = k0 + kk;
                Bs[kk][r] = (k < K) ? W[(size_t)(blockN + r) * ldb + k] : 0.f;
            }
            __syncthreads();
#pragma unroll
            for (int kk = 0; kk < BK; kk++) {
                float4 a0 = *reinterpret_cast<const float4*>(&As[kk][m0]);
                float4 a1 = *reinterpret_cast<const float4*>(&As[kk][m0 + 4]);
                float4 b0 = *reinterpret_cast<const float4*>(&Bs[kk][n0]);
                float4 b1 = *reinterpret_cast<const float4*>(&Bs[kk][n0 + 4]);
                float av[8] = {a0.x, a0.y, a0.z, a0.w, a1.x, a1.y, a1.z, a1.w};
                float bv[8] = {b0.x, b0.y, b0.z, b0.w, b1.x, b1.y, b1.z, b1.w};
#pragma unroll
                for (int i = 0; i < 8; i++)
#pragma unroll
                    for (int j = 0; j < 8; j++)
                        acc[i][j] += av[i] * bv[j];
            }
            __syncthreads();
        }
    }

#pragma unroll
    for (int j = 0; j < 8; j++) {
        int n = blockN + n0 + j;
        float bb = (bias1 ? bias1[n] : 0.f) + (bias2 ? bias2[n] : 0.f);
#pragma unroll
        for (int i = 0; i < 8; i++) {
            float v = acc[i][j] + bb;
            if (op == 1)      v = fmaxf(v, 0.f);
            else if (op == 2) v = tanhf(v);
            C[(size_t)(blockM + m0 + i) * ldc + n] = v;
        }
    }
}

// ---------------- small kernels ----------------
__global__ void prep_x30(const float* __restrict__ mi, const float* __restrict__ pop,
                         float* __restrict__ x30)
{
    int idx = blockIdx.x * blockDim.x + threadIdx.x;
    if (idx >= BATCH * TTL) return;
    int b = idx / TTL;
    int c = idx - b * TTL;
    x30[idx] = mi[b * IN_DIM + c] / pop[b];
}

__global__ void lstm_cell(const float* __restrict__ g, const float* __restrict__ c0,
                          float* __restrict__ xout, float* __restrict__ ts_out)
{
    int idx = blockIdx.x * blockDim.x + threadIdx.x;
    if (idx >= BATCH * HDIM) return;
    int b = idx >> 9;
    int h = idx & 511;
    const float* gr = g + (size_t)b * G4;
    float gi = gr[h];
    float gf = gr[HDIM + h];
    float gg = gr[2 * HDIM + h];
    float go = gr[3 * HDIM + h];
    float si = 1.f / (1.f + expf(-gi));
    float sf = 1.f / (1.f + expf(-gf));
    float so = 1.f / (1.f + expf(-go));
    float c  = sf * c0[idx] + si * tanhf(gg);
    float xv = so * tanhf(c);
    xout[idx] = xv;
    if (ts_out) ts_out[idx] = xv;
}

// raw = z @ ro_W2^T + ro_b2 ; dnn = sigmoid(raw*scale)*range
__global__ void raw_dnn_kernel(const float* __restrict__ z, const float* __restrict__ W2,
                               const float* __restrict__ b2, const float* __restrict__ rng,
                               const void* __restrict__ scale_ptr,
                               float* __restrict__ raw_out, float* __restrict__ dnn_out)
{
    __shared__ float zs[2 * HDIM];
    int b = blockIdx.x;
    const float* zr = z + (size_t)b * 2 * HDIM;
    for (int i = threadIdx.x; i < 2 * HDIM; i += blockDim.x) zs[i] = zr[i];
    __syncthreads();

    int warp = threadIdx.x >> 5;
    int lane = threadIdx.x & 31;

    // decode sigmoid_scale: works for int32(1), int64(1) low word, or float(1.0)
    int bits = *(const int*)scale_ptr;
    float f  = __int_as_float(bits);
    float af = fabsf(f);
    float s  = (af >= 1e-30f && af <= 1e30f) ? f : (float)bits;

    for (int o = warp; o < OUTD; o += 8) {
        const float* w = W2 + (size_t)o * 2 * HDIM;
        float acc = 0.f;
        for (int k = lane; k < 2 * HDIM; k += 32) acc += zs[k] * w[k];
#pragma unroll
        for (int off = 16; off; off >>= 1) acc += __shfl_xor_sync(0xffffffffu, acc, off);
        if (lane == 0) {
            float r = acc + b2[o];
            raw_out[(size_t)b * OUTD + o] = r;
            dnn_out[(size_t)b * OUTD + o] = (1.f / (1.f + expf(-r * s))) * rng[o];
        }
    }
}

// ---------------- ODE ----------------
#define LN2D 0.6931471805599453
#define C_RI  ((float)(LN2D / 5.0))
#define C_RD  ((float)(LN2D / 2.0))
#define C_RRI ((float)(LN2D / 10.0))
#define C_RRH ((float)(LN2D / 15.0))
#define C_RRV ((float)(LN2D / 10.0))
#define TWO_OVER_PI 0.6366197723675814f
#define HALF_PI     1.5707963267948966f

__device__ __forceinline__ void covid_deriv(const float y[16], float gam, float pdt,
                                            float aN, float r_dth, float d[16])
{
    float S = y[0], E = y[1], I = y[2];
    float AR = y[3], DHR = y[4], DQR = y[5], AD = y[6], DHD = y[7], DQD = y[8];
    float DVR = y[12], DVD = y[13];
    float inf = aN * gam * S * I;
    float det = C_RD * I;
    float d1m = det * (1.f - pdt);
    float dp  = det * pdt;
    d[0]  = -inf;
    d[1]  = inf - C_RI * E;
    d[2]  = C_RI * E - det;
    d[3]  = d1m * (1.0f - 0.2f) - C_RRI * AR;
    d[4]  = d1m * (0.2f * 0.15f) - C_RRH * DHR;
    d[5]  = d1m * (0.2f * (1.0f - 0.15f)) - C_RRI * DQR;
    d[6]  = dp * (1.0f - 0.2f) - r_dth * AD;
    d[7]  = dp * (0.2f * 0.15f) - r_dth * DHD;
    d[8]  = dp * (0.2f * (1.0f - 0.15f)) - r_dth * DQD;
    d[9]  = C_RRI * (AR + DQR) + C_RRH * DHR;
    d[10] = r_dth * (AD + DQD + DHD);
    d[11] = det * (0.2f * 0.15f);
    d[12] = d1m * (0.2f * 0.15f * 0.25f) - C_RRV * DVR;
    d[13] = dp * (0.2f * 0.15f * 0.25f) - r_dth * DVD;
    d[14] = r_dth * (DHD + DQD);
    d[15] = det * 0.2f;
}

__device__ __forceinline__ float gam_f(float t, float days, float rs20,
                                       float jump, float t_jump, float inv2s2)
{
    float a   = atanf((days - t) * rs20);
    float dtj = t - t_jump;
    return TWO_OVER_PI * a + 1.0f + jump * __expf(-dtj * dtj * inv2s2);
}

__device__ __forceinline__ float pdt_f(float t, float pc, float rdd20)
{
    return pc * (atanf(-t * rdd20) + HALF_PI) + 0.001f;
}

__global__ void ode_kernel(const float* __restrict__ pop, const float* __restrict__ ccn,
                           const float* __restrict__ mort, const float* __restrict__ dnn,
                           float* __restrict__ sol)
{
    int b = blockIdx.x * blockDim.x + threadIdx.x;
    if (b >= BATCH) return;
    const float* dn = dnn + (size_t)b * OUTD;
    float alpha = dn[11], days = dn[12], r_s = dn[13], r_dth = dn[14], p_dth = dn[15];
    float r_dthdecay = dn[16], k1 = dn[17], k2 = dn[18], jump = dn[19];
    float t_jump = dn[20], stdn = dn[21];

    float N    = pop[b];
    float PopI = ccn[b];
    float PopD = floorf(mort[b] * PopI);
    float R0   = (PopI - PopD > 5.0f * PopD) ? 5.0f * PopD : 0.0f;
    float PopCI = PopI - PopD - R0;
    float ciPD  = PopCI / 0.2f;
    float omp   = 1.0f - p_dth;

    float y[16];
    y[0]  = N - ciPD * (k1 + k2) - R0 / 0.2f - PopD / 0.2f;
    y[1]  = ciPD * k1;
    y[2]  = ciPD * k2;
    y[3]  = (ciPD - PopCI) * omp;
    y[4]  = PopCI * 0.15f * omp;
    y[5]  = PopCI * (1.0f - 0.15f) * omp;
    y[6]  = (ciPD - PopCI) * p_dth;
    y[7]  = PopCI * 0.15f * p_dth;
    y[8]  = PopCI * (1.0f - 0.15f) * p_dth;
    y[9]  = R0 / 0.2f;
    y[10] = PopD / 0.2f;
    y[11] = PopCI * 0.15f;
    y[12] = PopCI * 0.15f * 0.25f * omp;
    y[13] = PopCI * 0.15f * 0.25f * p_dth;
    y[14] = PopD;
    y[15] = PopI;

    float* srow = sol + (size_t)b * TPTS * 16;
#pragma unroll
    for (int i = 0; i < 16; i++) srow[i] = y[i];

    float aN     = alpha / N;
    float rs20   = r_s * (1.0f / 20.0f);
    float rdd20  = r_dthdecay * (1.0f / 20.0f);
    float inv2s2 = 1.0f / (2.0f * stdn * stdn);
    float pc     = TWO_OVER_PI * (p_dth - 0.001f);
    const float dt = 0.1f;

    for (int seg = 0; seg < TPTS - 1; seg++) {
        float t0 = (float)seg;
        for (int j = 0; j < 10; j++) {
            float t  = t0 + (float)j * dt;
            float tm = t + 0.05f;
            float tp = t + 0.1f;
            // gam/pdt depend only on t: 3 distinct times per substep (k2,k3 share)
            float g1 = gam_f(t,  days, rs20, jump, t_jump, inv2s2);
            float g2 = gam_f(tm, days, rs20, jump, t_jump, inv2s2);
            float g3 = gam_f(tp, days, rs20, jump, t_jump, inv2s2);
            float p1 = pdt_f(t,  pc, rdd20);
            float p2 = pdt_f(tm, pc, rdd20);
            float p3 = pdt_f(tp, pc, rdd20);

            float k[16], acc[16], yy[16];
            covid_deriv(y, g1, p1, aN, r_dth, k);
#pragma unroll
            for (int i = 0; i < 16; i++) { acc[i] = k[i]; yy[i] = y[i] + 0.05f * k[i]; }
            covid_deriv(yy, g2, p2, aN, r_dth, k);
#pragma unroll
            for (int i = 0; i < 16; i++) { acc[i] += 2.f * k[i]; yy[i] = y[i] + 0.05f * k[i]; }
            covid_deriv(yy, g2, p2, aN, r_dth, k);
#pragma unroll
            for (int i = 0; i < 16; i++) { acc[i] += 2.f * k[i]; yy[i] = y[i] + 0.1f * k[i]; }
            covid_deriv(yy, g3, p3, aN, r_dth, k);
#pragma unroll
            for (int i = 0; i < 16; i++) y[i] += (0.1f / 6.0f) * (acc[i] + k[i]);
        }
        float* o = srow + (size_t)(seg + 1) * 16;
#pragma unroll
        for (int i = 0; i < 16; i++) o[i] = y[i];
    }
}

// ---------------- launch ----------------
extern "C" void kernel_launch(void* const* d_in, const int* in_sizes, int n_in,
                              void* d_out, int out_size)
{
    const float* mi   = (const float*)d_in[0];
    const float* pop  = (const float*)d_in[1];
    const float* ccn  = (const float*)d_in[2];
    const float* mort = (const float*)d_in[3];
    const float* h0   = (const float*)d_in[4];
    const float* c0   = (const float*)d_in[5];
    const float* W_ih0= (const float*)d_in[6];
    const float* W_ihR= (const float*)d_in[7];
    const float* W_hh = (const float*)d_in[8];
    const float* b_ih = (const float*)d_in[9];
    const float* b_hh = (const float*)d_in[10];
    const float* mW1  = (const float*)d_in[11];
    const float* mb1  = (const float*)d_in[12];
    const float* mW2  = (const float*)d_in[13];
    const float* mb2  = (const float*)d_in[14];
    const float* rW1  = (const float*)d_in[15];
    const float* rb1  = (const float*)d_in[16];
    const float* rW2  = (const float*)d_in[17];
    const float* rb2  = (const float*)d_in[18];
    const float* rng  = (const float*)d_in[19];
    const void*  scl  = d_in[20];

    float* out  = (float*)d_out;
    float* sol  = out;                                   // (B, 90, 16)
    float* dnn  = out + (size_t)BATCH * TPTS * 16;       // (B, 23)
    float* ts   = dnn + (size_t)BATCH * OUTD;            // (B, 1, 512)
    float* raw  = ts  + (size_t)BATCH * HDIM;            // (B, 23)

    float *x30, *gate, *xb, *m1, *m2, *zb;
    cudaGetSymbolAddress((void**)&x30,  g_x30);
    cudaGetSymbolAddress((void**)&gate, g_gate);
    cudaGetSymbolAddress((void**)&xb,   g_x);
    cudaGetSymbolAddress((void**)&m1,   g_m1);
    cudaGetSymbolAddress((void**)&m2,   g_m2);
    cudaGetSymbolAddress((void**)&zb,   g_z);

    prep_x30<<<(BATCH * TTL + 255) / 256, 256>>>(mi, pop, x30);

    dim3 gGrid(G4 / BN, BATCH / BM);
    for (int l = 0; l < NL; l++) {
        const float* A1 = l ? xb : x30;
        int          K1 = l ? HDIM : TTL;
        const float* W1 = l ? (W_ihR + (size_t)(l - 1) * G4 * HDIM) : W_ih0;
        gemm_tn<<<gGrid, 256>>>(A1, K1, W1, K1, K1,
                                h0 + (size_t)l * BATCH * HDIM, HDIM,
                                W_hh + (size_t)l * G4 * HDIM, HDIM, HDIM,
                                b_ih + (size_t)l * G4, b_hh + (size_t)l * G4,
                                gate, G4, 0);
        lstm_cell<<<(BATCH * HDIM + 255) / 256, 256>>>(
            gate, c0 + (size_t)l * BATCH * HDIM, xb,
            (l == NL - 1) ? ts : nullptr);
    }

    dim3 mGrid(HDIM / BN, BATCH / BM);
    gemm_tn<<<mGrid, 256>>>(mi + TTL, IN_DIM, mW1, TTL, TTL,
                            nullptr, 0, nullptr, 0, 0,
                            mb1, nullptr, m1, HDIM, 1);
    gemm_tn<<<mGrid, 256>>>(m1, HDIM, mW2, HDIM, HDIM,
                            nullptr, 0, nullptr, 0, 0,
                            mb2, nullptr, m2, HDIM, 1);

    dim3 zGrid(2 * HDIM / BN, BATCH / BM);
    gemm_tn<<<zGrid, 256>>>(xb, HDIM, rW1, 2 * HDIM, HDIM,
                            m2, HDIM, rW1 + HDIM, 2 * HDIM, HDIM,
                            rb1, nullptr, zb, 2 * HDIM, 2);

    raw_dnn_kernel<<<BATCH, 256>>>(zb, rW2, rb2, rng, scl, raw, dnn);

    ode_kernel<<<(BATCH + 63) / 64, 64>>>(pop, ccn, mort, dnn, sol);
}

// round 5
// speedup vs baseline: 1.4896x; 1.4891x over previous
#include <cuda_runtime.h>
#include <cuda_bf16.h>
#include <math.h>
#include <stdint.h>

typedef __nv_bfloat16 bf16;

#define BATCH 2048
#define TTL   30
#define IN_DIM 60
#define HDIM  512
#define G4    2048
#define NL    5
#define OUTD  23
#define TPTS  90

// tcgen05 only exists on the 'a' target; harness PTX pass targets plain sm_103.
#if !defined(__CUDA_ARCH__) || defined(__CUDA_ARCH_FEAT_SM103_ALL) || defined(__CUDA_ARCH_FEAT_SM100_ALL)
#define TC_OK 1
#endif

// ============================ static scratch ============================
__device__ float g_gate[BATCH * G4];
__device__ float g_z   [BATCH * 2 * HDIM];
__device__ bf16  g_x30h[BATCH * 64],  g_x30l[BATCH * 64];
__device__ bf16  g_mih [BATCH * 64],  g_mil [BATCH * 64];
__device__ bf16  g_wi0h[G4 * 64],     g_wi0l[G4 * 64];
__device__ bf16  g_wirh[4 * G4 * HDIM], g_wirl[4 * G4 * HDIM];
__device__ bf16  g_whhh[5 * G4 * HDIM], g_whhl[5 * G4 * HDIM];
__device__ bf16  g_h0h [5 * BATCH * HDIM], g_h0l[5 * BATCH * HDIM];
__device__ bf16  g_mw1h[HDIM * 64],   g_mw1l[HDIM * 64];
__device__ bf16  g_mw2h[HDIM * HDIM], g_mw2l[HDIM * HDIM];
__device__ bf16  g_r1ah[2 * HDIM * HDIM], g_r1al[2 * HDIM * HDIM];
__device__ bf16  g_r1bh[2 * HDIM * HDIM], g_r1bl[2 * HDIM * HDIM];
__device__ bf16  g_xh  [BATCH * HDIM], g_xl[BATCH * HDIM];
__device__ bf16  g_m1h [BATCH * HDIM], g_m1l[BATCH * HDIM];
__device__ bf16  g_m2h [BATCH * HDIM], g_m2l[BATCH * HDIM];

// ============================ common helpers ============================
static __device__ __forceinline__ uint32_t smem_u32(const void* p) {
    uint32_t a;
    asm("{ .reg .u64 t; cvta.to.shared.u64 t, %1; cvt.u32.u64 %0, t; }" : "=r"(a) : "l"(p));
    return a;
}
static __device__ __forceinline__ void cpa16(uint32_t d, const void* s) {
    asm volatile("cp.async.cg.shared.global [%0], [%1], 16;" :: "r"(d), "l"(s));
}
static __device__ __forceinline__ void cp_commit() {
    asm volatile("cp.async.commit_group;" ::: "memory");
}
static __device__ __forceinline__ void cp_wait0() {
    asm volatile("cp.async.wait_group 0;" ::: "memory");
}
static __device__ __forceinline__ void cp_wait1() {
    asm volatile("cp.async.wait_group 1;" ::: "memory");
}
static __device__ __forceinline__ void ldsm4(uint32_t* r, uint32_t a) {
    asm volatile("ldmatrix.sync.aligned.m8n8.x4.shared.b16 {%0,%1,%2,%3}, [%4];"
                 : "=r"(r[0]), "=r"(r[1]), "=r"(r[2]), "=r"(r[3]) : "r"(a));
}
static __device__ __forceinline__ void mma16816(float* c, const uint32_t* a, const uint32_t* b) {
    asm volatile("mma.sync.aligned.m16n8k16.row.col.f32.bf16.bf16.f32 "
                 "{%0,%1,%2,%3}, {%4,%5,%6,%7}, {%8,%9}, {%0,%1,%2,%3};"
                 : "+f"(c[0]), "+f"(c[1]), "+f"(c[2]), "+f"(c[3])
                 : "r"(a[0]), "r"(a[1]), "r"(a[2]), "r"(a[3]), "r"(b[0]), "r"(b[1]));
}

#ifdef TC_OK
// ---- tcgen05-only helpers (compiled only on 'a' targets / host parse) ----
static __device__ __forceinline__ uint32_t elect_one() {
    uint32_t p;
    asm volatile("{ .reg .pred p; elect.sync _|p, 0xFFFFFFFF; selp.b32 %0, 1, 0, p; }" : "=r"(p));
    return p;
}
static __device__ __forceinline__ void mbar_init(uint32_t a, uint32_t cnt) {
    asm volatile("mbarrier.init.shared.b64 [%0], %1;" :: "r"(a), "r"(cnt) : "memory");
}
static __device__ __forceinline__ void mbar_wait(uint32_t a, uint32_t phase) {
    uint32_t done = 0;
    while (!done) {
        asm volatile("{\n\t.reg .pred p;\n\t"
            "mbarrier.try_wait.parity.acquire.cta.shared::cta.b64 p, [%1], %2, 0x989680;\n\t"
            "selp.b32 %0, 1, 0, p;\n\t}"
            : "=r"(done) : "r"(a), "r"(phase) : "memory");
    }
}
static __device__ __forceinline__ void tc_alloc(uint32_t slot, uint32_t n) {
    asm volatile("tcgen05.alloc.cta_group::1.sync.aligned.shared::cta.b32 [%0], %1;"
                 :: "r"(slot), "r"(n) : "memory");
}
static __device__ __forceinline__ void tc_dealloc(uint32_t t, uint32_t n) {
    asm volatile("tcgen05.dealloc.cta_group::1.sync.aligned.b32 %0, %1;" :: "r"(t), "r"(n));
}
static __device__ __forceinline__ void tc_relinq() {
    asm volatile("tcgen05.relinquish_alloc_permit.cta_group::1.sync.aligned;");
}
static __device__ __forceinline__ void tc_commit(uint32_t mbar) {
    asm volatile("tcgen05.commit.cta_group::1.mbarrier::arrive::one.shared::cluster.b64 [%0];"
                 :: "r"(mbar) : "memory");
}
static __device__ __forceinline__ void tc_fence_after() {
    asm volatile("tcgen05.fence::after_thread_sync;" ::: "memory");
}
static __device__ __forceinline__ void proxy_fence() {
    asm volatile("fence.proxy.async.shared::cta;" ::: "memory");
}
static __device__ __forceinline__ void mma_ss_f16(uint32_t d, uint64_t ad, uint64_t bd,
                                                  uint32_t idesc, uint32_t en) {
    asm volatile("{\n\t.reg .pred p;\n\tsetp.ne.u32 p, %4, 0;\n\t"
        "tcgen05.mma.cta_group::1.kind::f16 [%0], %1, %2, %3, {%5, %5, %5, %5}, p;\n\t}"
        :: "r"(d), "l"(ad), "l"(bd), "r"(idesc), "r"(en), "r"(0u) : "memory");
}
static __device__ __forceinline__ void ldtm32(uint32_t* r, uint32_t a) {
    asm volatile("tcgen05.ld.sync.aligned.32x32b.x32.b32 "
        "{%0,%1,%2,%3,%4,%5,%6,%7,%8,%9,%10,%11,%12,%13,%14,%15,"
        "%16,%17,%18,%19,%20,%21,%22,%23,%24,%25,%26,%27,%28,%29,%30,%31}, [%32];"
        : "=r"(r[0]),"=r"(r[1]),"=r"(r[2]),"=r"(r[3]),"=r"(r[4]),"=r"(r[5]),"=r"(r[6]),"=r"(r[7]),
          "=r"(r[8]),"=r"(r[9]),"=r"(r[10]),"=r"(r[11]),"=r"(r[12]),"=r"(r[13]),"=r"(r[14]),"=r"(r[15]),
          "=r"(r[16]),"=r"(r[17]),"=r"(r[18]),"=r"(r[19]),"=r"(r[20]),"=r"(r[21]),"=r"(r[22]),"=r"(r[23]),
          "=r"(r[24]),"=r"(r[25]),"=r"(r[26]),"=r"(r[27]),"=r"(r[28]),"=r"(r[29]),"=r"(r[30]),"=r"(r[31])
        : "r"(a));
}
static __device__ __forceinline__ void tc_wait_ld() {
    asm volatile("tcgen05.wait::ld.sync.aligned;" ::: "memory");
}
static constexpr uint64_t DESC_BASE =
    (uint64_t(2) << 61) | (uint64_t(1) << 46) | (uint64_t(64) << 32) | (uint64_t(1) << 16);
static __device__ __forceinline__ uint64_t make_desc(uint32_t a) {
    return DESC_BASE | ((uint64_t)(a >> 4) & 0x3FFF);
}
#define GEMM_IDESC ((1u<<4)|(1u<<7)|(1u<<10)|((128u/8)<<17)|((128u/16)<<24))
#endif // TC_OK

// ============================ GEMM kernel ============================
struct Seg { const bf16* A; const bf16* B; int K; };
struct GArgs {
    Seg s[6]; int nseg;
    const float* bias1; const float* bias2;
    float* Cf; bf16* Ch; bf16* Cl;
    int ldc; int op;  // 0 none, 1 relu, 2 tanh
};
#define SM_STAGE0 1024
#define SM_STAGEB 32768
#define GEMM_SMEM (1024 + 128 * 129 * 4 + 256)

__global__ __launch_bounds__(256)
void gemm_tc(GArgs args)
{
    extern __shared__ __align__(1024) char smem[];
    const uint32_t sb = smem_u32(smem);
    const int tid = threadIdx.x;
    const int wid = tid >> 5;
    const int lane = tid & 31;
    const int bM = blockIdx.y * 128;
    const int bN = blockIdx.x * 128;

#ifdef TC_OK
    // ======================= tcgen05 path (sm_103a) =======================
    if (wid == 0) tc_alloc(sb + 0, 128);
    if (tid == 0) { mbar_init(sb + 16, 1); mbar_init(sb + 24, 1); }
    __syncthreads();
    uint32_t tmem;
    asm volatile("ld.shared.b32 %0, [%1];" : "=r"(tmem) : "r"(sb + 0));

    int c = 0, ph0 = 0, ph1 = 0;
    for (int sg = 0; sg < args.nseg; sg++) {
        const bf16* A = args.s[sg].A;
        const bf16* B = args.s[sg].B;
        const int K = args.s[sg].K;
        for (int k0 = 0; k0 < K; k0 += 64) {
            const int slot = c & 1;
            if (c >= 2) {
                if (slot) { mbar_wait(sb + 24, ph1); ph1 ^= 1; }
                else      { mbar_wait(sb + 16, ph0); ph0 ^= 1; }
            }
            char* stA = smem + SM_STAGE0 + slot * SM_STAGEB;
            char* stB = stA + 16384;
#pragma unroll
            for (int i = 0; i < 4; i++) {
                int idx = tid + i * 256;
                int row = idx >> 3, g = idx & 7;
                uint4 v = *reinterpret_cast<const uint4*>(A + (size_t)(bM + row) * K + k0 + g * 8);
                uint32_t off = (uint32_t)(row * 128 + g * 16);
                off ^= (off >> 3) & 0x70;
                *reinterpret_cast<uint4*>(stA + off) = v;
            }
#pragma unroll
            for (int i = 0; i < 4; i++) {
                int idx = tid + i * 256;
                int row = idx >> 3, g = idx & 7;
                uint4 v = *reinterpret_cast<const uint4*>(B + (size_t)(bN + row) * K + k0 + g * 8);
                uint32_t off = (uint32_t)(row * 128 + g * 16);
                off ^= (off >> 3) & 0x70;
                *reinterpret_cast<uint4*>(stB + off) = v;
            }
            proxy_fence();
            __syncthreads();
            if (wid == 0 && elect_one()) {
                uint64_t ad = make_desc(sb + SM_STAGE0 + slot * SM_STAGEB);
                uint64_t bd = ad + (16384 >> 4);
#pragma unroll
                for (int kk = 0; kk < 4; kk++)
                    mma_ss_f16(tmem, ad + 2 * kk, bd + 2 * kk, GEMM_IDESC,
                               (c > 0 || kk > 0) ? 1u : 0u);
                tc_commit(sb + 16 + slot * 8);
            }
            c++;
        }
    }
    {
        int s0 = c & 1;
        if (s0) { mbar_wait(sb + 24, ph1); ph1 ^= 1; } else { mbar_wait(sb + 16, ph0); ph0 ^= 1; }
        int s1 = (c + 1) & 1;
        if (s1) { mbar_wait(sb + 24, ph1); ph1 ^= 1; } else { mbar_wait(sb + 16, ph0); ph0 ^= 1; }
    }
    tc_fence_after();
    __syncthreads();

    float* epi = reinterpret_cast<float*>(smem + SM_STAGE0);
    if (wid < 4) {
        int row = wid * 32 + lane;
#pragma unroll
        for (int nb = 0; nb < 4; nb++) {
            uint32_t r[32];
            ldtm32(r, tmem + nb * 32);
            tc_wait_ld();
#pragma unroll
            for (int j = 0; j < 32; j++)
                epi[row * 129 + nb * 32 + j] = __uint_as_float(r[j]);
        }
    }
    __syncthreads();

#pragma unroll 1
    for (int it = 0; it < 16; it++) {
        int flat = (it * 256 + tid) * 4;
        int row = flat >> 7, col = flat & 127;
        float v[4];
#pragma unroll
        for (int i = 0; i < 4; i++) {
            float x = epi[row * 129 + col + i];
            if (args.bias1) x += args.bias1[bN + col + i];
            if (args.bias2) x += args.bias2[bN + col + i];
            if (args.op == 1)      x = fmaxf(x, 0.f);
            else if (args.op == 2) x = tanhf(x);
            v[i] = x;
        }
        size_t base = (size_t)(bM + row) * args.ldc + bN + col;
        if (args.Cf)
            *reinterpret_cast<float4*>(args.Cf + base) = make_float4(v[0], v[1], v[2], v[3]);
        if (args.Ch) {
            uint32_t hp[2], lp[2];
#pragma unroll
            for (int h = 0; h < 2; h++) {
                bf16 a = __float2bfloat16(v[2*h]);
                bf16 b = __float2bfloat16(v[2*h+1]);
                bf16 la = __float2bfloat16(v[2*h]   - __bfloat162float(a));
                bf16 lb = __float2bfloat16(v[2*h+1] - __bfloat162float(b));
                hp[h] = (uint32_t)__bfloat16_as_ushort(a) | ((uint32_t)__bfloat16_as_ushort(b) << 16);
                lp[h] = (uint32_t)__bfloat16_as_ushort(la) | ((uint32_t)__bfloat16_as_ushort(lb) << 16);
            }
            *reinterpret_cast<uint2*>(args.Ch + base) = make_uint2(hp[0], hp[1]);
            *reinterpret_cast<uint2*>(args.Cl + base) = make_uint2(lp[0], lp[1]);
        }
    }
    __syncthreads();
    if (wid == 0) { tc_relinq(); tc_dealloc(tmem, 128); }

#else
    // ======================= HMMA mma.sync path (plain sm_103) =======================
    // CTA tile 128x128, warp tile 32x64 (warps 4x2), BK=32 bf16, 2-stage cp.async.
    // smem per stage: A[128][32] + B[128][32] bf16, row stride 40 elems (80B, conflict-free ldmatrix).
    int segBase[7];
    segBase[0] = 0;
#pragma unroll
    for (int i = 0; i < 6; i++)
        segBase[i + 1] = segBase[i] + ((i < args.nseg) ? (args.s[i].K >> 5) : 0);
    const int nch = segBase[6];

    const int wm = (wid >> 1) * 32;
    const int wn = (wid & 1) * 64;

    float ac[2][8][4];
#pragma unroll
    for (int mt = 0; mt < 2; mt++)
#pragma unroll
        for (int nt = 0; nt < 8; nt++)
#pragma unroll
            for (int i = 0; i < 4; i++) ac[mt][nt][i] = 0.f;

    auto loadChunk = [&](int cc) {
        int s = 0;
#pragma unroll
        for (int i = 0; i < 5; i++) if (cc >= segBase[i + 1]) s = i + 1;
        const bf16* A = args.s[s].A;
        const bf16* B = args.s[s].B;
        const int K = args.s[s].K;
        const int k0 = (cc - segBase[s]) * 32;
        uint32_t st = sb + (uint32_t)(cc & 1) * 20480u;
#pragma unroll
        for (int i = 0; i < 2; i++) {
            int ch = tid + i * 256;
            int row = ch >> 2, cb = ch & 3;
            cpa16(st + (uint32_t)(row * 80 + cb * 16),
                  A + (size_t)(bM + row) * K + k0 + cb * 8);
        }
#pragma unroll
        for (int i = 0; i < 2; i++) {
            int ch = tid + i * 256;
            int row = ch >> 2, cb = ch & 3;
            cpa16(st + 10240u + (uint32_t)(row * 80 + cb * 16),
                  B + (size_t)(bN + row) * K + k0 + cb * 8);
        }
    };

    loadChunk(0); cp_commit();
    for (int cc = 0; cc < nch; cc++) {
        const bool more = (cc + 1 < nch);
        if (more) { loadChunk(cc + 1); cp_commit(); }
        if (more) cp_wait1(); else cp_wait0();
        __syncthreads();
        uint32_t stA = sb + (uint32_t)(cc & 1) * 20480u;
        uint32_t stB = stA + 10240u;
#pragma unroll
        for (int kk = 0; kk < 32; kk += 16) {
            uint32_t af[2][4], bfr[4][4];
#pragma unroll
            for (int mt = 0; mt < 2; mt++)
                ldsm4(af[mt], stA + (uint32_t)((wm + mt * 16 + (lane & 15)) * 80
                                               + (kk + (lane >> 4) * 8) * 2));
#pragma unroll
            for (int p = 0; p < 4; p++)
                ldsm4(bfr[p], stB + (uint32_t)((wn + p * 16 + (lane & 7) + ((lane >> 4) & 1) * 8) * 80
                                               + (kk + ((lane >> 3) & 1) * 8) * 2));
#pragma unroll
            for (int mt = 0; mt < 2; mt++)
#pragma unroll
                for (int nt = 0; nt < 8; nt++)
                    mma16816(ac[mt][nt], af[mt], &bfr[nt >> 1][(nt & 1) * 2]);
        }
        __syncthreads();
    }

    auto storePair = [&](int row, int col, float v0, float v1) {
        if (args.bias1) { v0 += args.bias1[col]; v1 += args.bias1[col + 1]; }
        if (args.bias2) { v0 += args.bias2[col]; v1 += args.bias2[col + 1]; }
        if (args.op == 1)      { v0 = fmaxf(v0, 0.f); v1 = fmaxf(v1, 0.f); }
        else if (args.op == 2) { v0 = tanhf(v0); v1 = tanhf(v1); }
        size_t base = (size_t)row * args.ldc + col;
        if (args.Cf)
            *reinterpret_cast<float2*>(args.Cf + base) = make_float2(v0, v1);
        if (args.Ch) {
            bf16 h0 = __float2bfloat16(v0), h1 = __float2bfloat16(v1);
            bf16 l0 = __float2bfloat16(v0 - __bfloat162float(h0));
            bf16 l1 = __float2bfloat16(v1 - __bfloat162float(h1));
            *reinterpret_cast<uint32_t*>(args.Ch + base) =
                (uint32_t)__bfloat16_as_ushort(h0) | ((uint32_t)__bfloat16_as_ushort(h1) << 16);
            *reinterpret_cast<uint32_t*>(args.Cl + base) =
                (uint32_t)__bfloat16_as_ushort(l0) | ((uint32_t)__bfloat16_as_ushort(l1) << 16);
        }
    };
#pragma unroll
    for (int mt = 0; mt < 2; mt++)
#pragma unroll
        for (int nt = 0; nt < 8; nt++) {
            int row = bM + wm + mt * 16 + (lane >> 2);
            int col = bN + wn + nt * 8 + 2 * (lane & 3);
            storePair(row,     col, ac[mt][nt][0], ac[mt][nt][1]);
            storePair(row + 8, col, ac[mt][nt][2], ac[mt][nt][3]);
        }
#endif
}

// ============================ conversion ============================
__global__ void conv_hl(const float* __restrict__ src, int rows, int Ks, int ld, int Kd,
                        bf16* __restrict__ h, bf16* __restrict__ l, const float* __restrict__ divr)
{
    int idx = blockIdx.x * blockDim.x + threadIdx.x;
    if (idx >= rows * Kd) return;
    int r = idx / Kd, k = idx - r * Kd;
    float v = (k < Ks) ? src[(size_t)r * ld + k] : 0.f;
    if (divr) v /= divr[r];
    bf16 hb = __float2bfloat16(v);
    h[idx] = hb;
    l[idx] = __float2bfloat16(v - __bfloat162float(hb));
}

__global__ void lstm_cell(const float* __restrict__ g, const float* __restrict__ c0,
                          bf16* __restrict__ xh, bf16* __restrict__ xl,
                          float* __restrict__ ts_out)
{
    int idx = blockIdx.x * blockDim.x + threadIdx.x;
    if (idx >= BATCH * HDIM) return;
    int b = idx >> 9;
    int hh = idx & 511;
    const float* gr = g + (size_t)b * G4;
    float gi = gr[hh], gf = gr[HDIM + hh], gg = gr[2 * HDIM + hh], go = gr[3 * HDIM + hh];
    float si = 1.f / (1.f + expf(-gi));
    float sf = 1.f / (1.f + expf(-gf));
    float so = 1.f / (1.f + expf(-go));
    float cc = sf * c0[idx] + si * tanhf(gg);
    float xv = so * tanhf(cc);
    bf16 hb = __float2bfloat16(xv);
    xh[idx] = hb;
    xl[idx] = __float2bfloat16(xv - __bfloat162float(hb));
    if (ts_out) ts_out[idx] = xv;
}

__global__ void raw_dnn_kernel(const float* __restrict__ z, const float* __restrict__ W2,
                               const float* __restrict__ b2, const float* __restrict__ rng,
                               const void* __restrict__ scale_ptr,
                               float* __restrict__ raw_out, float* __restrict__ dnn_out)
{
    __shared__ float zs[2 * HDIM];
    int b = blockIdx.x;
    const float* zr = z + (size_t)b * 2 * HDIM;
    for (int i = threadIdx.x; i < 2 * HDIM; i += blockDim.x) zs[i] = zr[i];
    __syncthreads();
    int warp = threadIdx.x >> 5, lane = threadIdx.x & 31;
    int bits = *(const int*)scale_ptr;
    float f = __int_as_float(bits);
    float af = fabsf(f);
    float s = (af >= 1e-30f && af <= 1e30f) ? f : (float)bits;
    for (int o = warp; o < OUTD; o += 8) {
        const float* w = W2 + (size_t)o * 2 * HDIM;
        float acc = 0.f;
        for (int k = lane; k < 2 * HDIM; k += 32) acc += zs[k] * w[k];
#pragma unroll
        for (int off = 16; off; off >>= 1) acc += __shfl_xor_sync(0xffffffffu, acc, off);
        if (lane == 0) {
            float r = acc + b2[o];
            raw_out[(size_t)b * OUTD + o] = r;
            dnn_out[(size_t)b * OUTD + o] = (1.f / (1.f + expf(-r * s))) * rng[o];
        }
    }
}

// ============================ ODE ============================
#define LN2D 0.6931471805599453
#define C_RI  ((float)(LN2D / 5.0))
#define C_RD  ((float)(LN2D / 2.0))
#define C_RRI ((float)(LN2D / 10.0))
#define C_RRH ((float)(LN2D / 15.0))
#define C_RRV ((float)(LN2D / 10.0))
#define TWO_OVER_PI 0.6366197723675814f
#define HALF_PI     1.5707963267948966f

__device__ __forceinline__ void covid_deriv(const float y[16], float gam, float pdt,
                                            float aN, float r_dth, float d[16])
{
    float S = y[0], E = y[1], I = y[2];
    float AR = y[3], DHR = y[4], DQR = y[5], AD = y[6], DHD = y[7], DQD = y[8];
    float DVR = y[12], DVD = y[13];
    float inf = aN * gam * S * I;
    float det = C_RD * I;
    float d1m = det * (1.f - pdt);
    float dp  = det * pdt;
    d[0] = -inf;
    d[1] = inf - C_RI * E;
    d[2] = C_RI * E - det;
    d[3] = d1m * 0.8f - C_RRI * AR;
    d[4] = d1m * 0.03f - C_RRH * DHR;
    d[5] = d1m * 0.17f - C_RRI * DQR;
    d[6] = dp * 0.8f - r_dth * AD;
    d[7] = dp * 0.03f - r_dth * DHD;
    d[8] = dp * 0.17f - r_dth * DQD;
    d[9] = C_RRI * (AR + DQR) + C_RRH * DHR;
    d[10] = r_dth * (AD + DQD + DHD);
    d[11] = det * 0.03f;
    d[12] = d1m * 0.0075f - C_RRV * DVR;
    d[13] = dp * 0.0075f - r_dth * DVD;
    d[14] = r_dth * (DHD + DQD);
    d[15] = det * 0.2f;
}
__device__ __forceinline__ float gam_f(float t, float days, float rs20,
                                       float jump, float t_jump, float inv2s2)
{
    float dtj = t - t_jump;
    return TWO_OVER_PI * atanf((days - t) * rs20) + 1.0f + jump * __expf(-dtj * dtj * inv2s2);
}
__device__ __forceinline__ float pdt_f(float t, float pc, float rdd20)
{
    return pc * (atanf(-t * rdd20) + HALF_PI) + 0.001f;
}

__global__ void ode_kernel(const float* __restrict__ pop, const float* __restrict__ ccn,
                           const float* __restrict__ mort, const float* __restrict__ dnn,
                           float* __restrict__ sol)
{
    int b = blockIdx.x * blockDim.x + threadIdx.x;
    if (b >= BATCH) return;
    const float* dn = dnn + (size_t)b * OUTD;
    float alpha = dn[11], days = dn[12], r_s = dn[13], r_dth = dn[14], p_dth = dn[15];
    float r_dthdecay = dn[16], k1 = dn[17], k2 = dn[18], jump = dn[19];
    float t_jump = dn[20], stdn = dn[21];

    float N = pop[b];
    float PopI = ccn[b];
    float PopD = floorf(mort[b] * PopI);
    float R0 = (PopI - PopD > 5.0f * PopD) ? 5.0f * PopD : 0.0f;
    float PopCI = PopI - PopD - R0;
    float ciPD = PopCI / 0.2f;
    float omp = 1.0f - p_dth;

    float y[16];
    y[0] = N - ciPD * (k1 + k2) - R0 / 0.2f - PopD / 0.2f;
    y[1] = ciPD * k1;  y[2] = ciPD * k2;
    y[3] = (ciPD - PopCI) * omp;
    y[4] = PopCI * 0.15f * omp;
    y[5] = PopCI * 0.85f * omp;
    y[6] = (ciPD - PopCI) * p_dth;
    y[7] = PopCI * 0.15f * p_dth;
    y[8] = PopCI * 0.85f * p_dth;
    y[9] = R0 / 0.2f;  y[10] = PopD / 0.2f;
    y[11] = PopCI * 0.15f;
    y[12] = PopCI * 0.0375f * omp;
    y[13] = PopCI * 0.0375f * p_dth;
    y[14] = PopD;  y[15] = PopI;

    float* srow = sol + (size_t)b * TPTS * 16;
#pragma unroll
    for (int i = 0; i < 16; i++) srow[i] = y[i];

    float aN = alpha / N;
    float rs20 = r_s * 0.05f;
    float rdd20 = r_dthdecay * 0.05f;
    float inv2s2 = 1.0f / (2.0f * stdn * stdn);
    float pc = TWO_OVER_PI * (p_dth - 0.001f);

    for (int seg = 0; seg < TPTS - 1; seg++) {
        float t0 = (float)seg;
        for (int j = 0; j < 10; j++) {
            float t = t0 + (float)j * 0.1f;
            float g1 = gam_f(t, days, rs20, jump, t_jump, inv2s2);
            float g2 = gam_f(t + 0.05f, days, rs20, jump, t_jump, inv2s2);
            float g3 = gam_f(t + 0.1f, days, rs20, jump, t_jump, inv2s2);
            float p1 = pdt_f(t, pc, rdd20);
            float p2 = pdt_f(t + 0.05f, pc, rdd20);
            float p3 = pdt_f(t + 0.1f, pc, rdd20);
            float k[16], acc[16], yy[16];
            covid_deriv(y, g1, p1, aN, r_dth, k);
#pragma unroll
            for (int i = 0; i < 16; i++) { acc[i] = k[i]; yy[i] = y[i] + 0.05f * k[i]; }
            covid_deriv(yy, g2, p2, aN, r_dth, k);
#pragma unroll
            for (int i = 0; i < 16; i++) { acc[i] += 2.f * k[i]; yy[i] = y[i] + 0.05f * k[i]; }
            covid_deriv(yy, g2, p2, aN, r_dth, k);
#pragma unroll
            for (int i = 0; i < 16; i++) { acc[i] += 2.f * k[i]; yy[i] = y[i] + 0.1f * k[i]; }
            covid_deriv(yy, g3, p3, aN, r_dth, k);
#pragma unroll
            for (int i = 0; i < 16; i++) y[i] += (0.1f / 6.0f) * (acc[i] + k[i]);
        }
        float* o = srow + (size_t)(seg + 1) * 16;
#pragma unroll
        for (int i = 0; i < 16; i++) o[i] = y[i];
    }
}

// ============================ launch ============================
static void* sym(const void* s) { void* p; cudaGetSymbolAddress(&p, s); return p; }

extern "C" void kernel_launch(void* const* d_in, const int* in_sizes, int n_in,
                              void* d_out, int out_size)
{
    const float* mi    = (const float*)d_in[0];
    const float* pop   = (const float*)d_in[1];
    const float* ccn   = (const float*)d_in[2];
    const float* mort  = (const float*)d_in[3];
    const float* h0    = (const float*)d_in[4];
    const float* c0    = (const float*)d_in[5];
    const float* W_ih0 = (const float*)d_in[6];
    const float* W_ihR = (const float*)d_in[7];
    const float* W_hh  = (const float*)d_in[8];
    const float* b_ih  = (const float*)d_in[9];
    const float* b_hh  = (const float*)d_in[10];
    const float* mW1   = (const float*)d_in[11];
    const float* mb1   = (const float*)d_in[12];
    const float* mW2   = (const float*)d_in[13];
    const float* mb2   = (const float*)d_in[14];
    const float* rW1   = (const float*)d_in[15];
    const float* rb1   = (const float*)d_in[16];
    const float* rW2   = (const float*)d_in[17];
    const float* rb2   = (const float*)d_in[18];
    const float* rng   = (const float*)d_in[19];
    const void*  scl   = d_in[20];

    float* out = (float*)d_out;
    float* sol = out;
    float* dnn = out + (size_t)BATCH * TPTS * 16;
    float* ts  = dnn + (size_t)BATCH * OUTD;
    float* raw = ts  + (size_t)BATCH * HDIM;

    float* gate = (float*)sym(g_gate);
    float* zb   = (float*)sym(g_z);
    bf16 *x30h = (bf16*)sym(g_x30h), *x30l = (bf16*)sym(g_x30l);
    bf16 *mih  = (bf16*)sym(g_mih),  *mil  = (bf16*)sym(g_mil);
    bf16 *wi0h = (bf16*)sym(g_wi0h), *wi0l = (bf16*)sym(g_wi0l);
    bf16 *wirh = (bf16*)sym(g_wirh), *wirl = (bf16*)sym(g_wirl);
    bf16 *whhh = (bf16*)sym(g_whhh), *whhl = (bf16*)sym(g_whhl);
    bf16 *h0h  = (bf16*)sym(g_h0h),  *h0l  = (bf16*)sym(g_h0l);
    bf16 *mw1h = (bf16*)sym(g_mw1h), *mw1l = (bf16*)sym(g_mw1l);
    bf16 *mw2h = (bf16*)sym(g_mw2h), *mw2l = (bf16*)sym(g_mw2l);
    bf16 *r1ah = (bf16*)sym(g_r1ah), *r1al = (bf16*)sym(g_r1al);
    bf16 *r1bh = (bf16*)sym(g_r1bh), *r1bl = (bf16*)sym(g_r1bl);
    bf16 *xh   = (bf16*)sym(g_xh),   *xl   = (bf16*)sym(g_xl);
    bf16 *m1h  = (bf16*)sym(g_m1h),  *m1l  = (bf16*)sym(g_m1l);
    bf16 *m2h  = (bf16*)sym(g_m2h),  *m2l  = (bf16*)sym(g_m2l);

    cudaFuncSetAttribute(gemm_tc, cudaFuncAttributeMaxDynamicSharedMemorySize, GEMM_SMEM);

    auto CV = [&](const float* s, int rows, int Ks, int ld, int Kd, bf16* h, bf16* l,
                  const float* dv) {
        int n = rows * Kd;
        conv_hl<<<(n + 255) / 256, 256>>>(s, rows, Ks, ld, Kd, h, l, dv);
    };
    CV(mi,          BATCH,     TTL,  IN_DIM, 64,   x30h, x30l, pop);
    CV(mi + TTL,    BATCH,     30,   IN_DIM, 64,   mih,  mil,  nullptr);
    CV(W_ih0,       G4,        TTL,  TTL,    64,   wi0h, wi0l, nullptr);
    CV(W_ihR,       4 * G4,    HDIM, HDIM,   HDIM, wirh, wirl, nullptr);
    CV(W_hh,        5 * G4,    HDIM, HDIM,   HDIM, whhh, whhl, nullptr);
    CV(h0,          5 * BATCH, HDIM, HDIM,   HDIM, h0h,  h0l,  nullptr);
    CV(mW1,         HDIM,      30,   30,     64,   mw1h, mw1l, nullptr);
    CV(mW2,         HDIM,      HDIM, HDIM,   HDIM, mw2h, mw2l, nullptr);
    CV(rW1,         2 * HDIM,  HDIM, 2*HDIM, HDIM, r1ah, r1al, nullptr);
    CV(rW1 + HDIM,  2 * HDIM,  HDIM, 2*HDIM, HDIM, r1bh, r1bl, nullptr);

    auto GL = [&](dim3 grid, Seg* sg, int ns, const float* b1, const float* b2,
                  float* Cf, bf16* Ch, bf16* Cl, int ldc, int op) {
        GArgs a = {};
        for (int i = 0; i < ns; i++) a.s[i] = sg[i];
        a.nseg = ns; a.bias1 = b1; a.bias2 = b2;
        a.Cf = Cf; a.Ch = Ch; a.Cl = Cl; a.ldc = ldc; a.op = op;
        gemm_tc<<<grid, 256, GEMM_SMEM>>>(a);
    };

    dim3 gGrid(G4 / 128, BATCH / 128);
    for (int l = 0; l < NL; l++) {
        bf16* ah = l ? xh : x30h;
        bf16* al = l ? xl : x30l;
        int   Kx = l ? HDIM : 64;
        bf16* wh = l ? (wirh + (size_t)(l - 1) * G4 * HDIM) : wi0h;
        bf16* wl = l ? (wirl + (size_t)(l - 1) * G4 * HDIM) : wi0l;
        bf16* hh = h0h + (size_t)l * BATCH * HDIM;
        bf16* hl = h0l + (size_t)l * BATCH * HDIM;
        bf16* Wh = whhh + (size_t)l * G4 * HDIM;
        bf16* Wl = whhl + (size_t)l * G4 * HDIM;
        Seg sg[6] = { {ah, wh, Kx}, {al, wh, Kx}, {ah, wl, Kx},
                      {hh, Wh, HDIM}, {hl, Wh, HDIM}, {hh, Wl, HDIM} };
        GL(gGrid, sg, 6, b_ih + (size_t)l * G4, b_hh + (size_t)l * G4,
           gate, nullptr, nullptr, G4, 0);
        lstm_cell<<<(BATCH * HDIM + 255) / 256, 256>>>(
            gate, c0 + (size_t)l * BATCH * HDIM, xh, xl, (l == NL - 1) ? ts : nullptr);
    }

    dim3 mGrid(HDIM / 128, BATCH / 128);
    { Seg sg[3] = { {mih, mw1h, 64}, {mil, mw1h, 64}, {mih, mw1l, 64} };
      GL(mGrid, sg, 3, mb1, nullptr, nullptr, m1h, m1l, HDIM, 1); }
    { Seg sg[3] = { {m1h, mw2h, HDIM}, {m1l, mw2h, HDIM}, {m1h, mw2l, HDIM} };
      GL(mGrid, sg, 3, mb2, nullptr, nullptr, m2h, m2l, HDIM, 1); }

    dim3 zGrid(2 * HDIM / 128, BATCH / 128);
    { Seg sg[6] = { {xh, r1ah, HDIM}, {xl, r1ah, HDIM}, {xh, r1al, HDIM},
                    {m2h, r1bh, HDIM}, {m2l, r1bh, HDIM}, {m2h, r1bl, HDIM} };
      GL(zGrid, sg, 6, rb1, nullptr, zb, nullptr, nullptr, 2 * HDIM, 2); }

    raw_dnn_kernel<<<BATCH, 256>>>(zb, rW2, rb2, rng, scl, raw, dnn);
    ode_kernel<<<(BATCH + 63) / 64, 64>>>(pop, ccn, mort, dnn, sol);
}

// round 8
// speedup vs baseline: 1.8272x; 1.2267x over previous
#include <cuda_runtime.h>
#include <cuda_bf16.h>
#include <math.h>
#include <stdint.h>

typedef __nv_bfloat16 bf16;

#define BATCH 2048
#define TTL   30
#define IN_DIM 60
#define HDIM  512
#define G4    2048
#define NL    5
#define OUTD  23
#define TPTS  90

#if !defined(__CUDA_ARCH__) || defined(__CUDA_ARCH_FEAT_SM103_ALL) || defined(__CUDA_ARCH_FEAT_SM100_ALL)
#define TC_OK 1
#endif

// ============================ static scratch ============================
__device__ float g_z    [BATCH * 2 * HDIM];
__device__ float g_biasp[NL * G4];
__device__ bf16  g_x30h[BATCH * 64],  g_x30l[BATCH * 64];
__device__ bf16  g_mih [BATCH * 64],  g_mil [BATCH * 64];
__device__ bf16  g_wi0h[G4 * 64],     g_wi0l[G4 * 64];
__device__ bf16  g_wirh[4 * G4 * HDIM], g_wirl[4 * G4 * HDIM];
__device__ bf16  g_whhh[5 * G4 * HDIM], g_whhl[5 * G4 * HDIM];
__device__ bf16  g_h0h [5 * BATCH * HDIM], g_h0l[5 * BATCH * HDIM];
__device__ bf16  g_mw1h[HDIM * 64],   g_mw1l[HDIM * 64];
__device__ bf16  g_mw2h[HDIM * HDIM], g_mw2l[HDIM * HDIM];
__device__ bf16  g_r1ah[2 * HDIM * HDIM], g_r1al[2 * HDIM * HDIM];
__device__ bf16  g_r1bh[2 * HDIM * HDIM], g_r1bl[2 * HDIM * HDIM];
// ping-pong x buffers (avoids in-place read/write race in fused LSTM layers)
__device__ bf16  g_xAh [BATCH * HDIM], g_xAl[BATCH * HDIM];
__device__ bf16  g_xBh [BATCH * HDIM], g_xBl[BATCH * HDIM];
__device__ bf16  g_m1h [BATCH * HDIM], g_m1l[BATCH * HDIM];
__device__ bf16  g_m2h [BATCH * HDIM], g_m2l[BATCH * HDIM];

// ============================ common helpers ============================
static __device__ __forceinline__ uint32_t smem_u32(const void* p) {
    uint32_t a;
    asm("{ .reg .u64 t; cvta.to.shared.u64 t, %1; cvt.u32.u64 %0, t; }" : "=r"(a) : "l"(p));
    return a;
}
static __device__ __forceinline__ void cpa16(uint32_t d, const void* s) {
    asm volatile("cp.async.cg.shared.global [%0], [%1], 16;" :: "r"(d), "l"(s));
}
static __device__ __forceinline__ void cp_commit() {
    asm volatile("cp.async.commit_group;" ::: "memory");
}
static __device__ __forceinline__ void cp_wait0() {
    asm volatile("cp.async.wait_group 0;" ::: "memory");
}
static __device__ __forceinline__ void cp_wait1() {
    asm volatile("cp.async.wait_group 1;" ::: "memory");
}
static __device__ __forceinline__ void ldsm4(uint32_t* r, uint32_t a) {
    asm volatile("ldmatrix.sync.aligned.m8n8.x4.shared.b16 {%0,%1,%2,%3}, [%4];"
                 : "=r"(r[0]), "=r"(r[1]), "=r"(r[2]), "=r"(r[3]) : "r"(a));
}
static __device__ __forceinline__ void mma16816(float* c, const uint32_t* a, const uint32_t* b) {
    asm volatile("mma.sync.aligned.m16n8k16.row.col.f32.bf16.bf16.f32 "
                 "{%0,%1,%2,%3}, {%4,%5,%6,%7}, {%8,%9}, {%0,%1,%2,%3};"
                 : "+f"(c[0]), "+f"(c[1]), "+f"(c[2]), "+f"(c[3])
                 : "r"(a[0]), "r"(a[1]), "r"(a[2]), "r"(a[3]), "r"(b[0]), "r"(b[1]));
}
static __device__ __forceinline__ float sigf(float x) { return 1.f / (1.f + expf(-x)); }

#ifdef TC_OK
static __device__ __forceinline__ uint32_t elect_one() {
    uint32_t p;
    asm volatile("{ .reg .pred p; elect.sync _|p, 0xFFFFFFFF; selp.b32 %0, 1, 0, p; }" : "=r"(p));
    return p;
}
static __device__ __forceinline__ void mbar_init(uint32_t a, uint32_t cnt) {
    asm volatile("mbarrier.init.shared.b64 [%0], %1;" :: "r"(a), "r"(cnt) : "memory");
}
static __device__ __forceinline__ void mbar_wait(uint32_t a, uint32_t phase) {
    uint32_t done = 0;
    while (!done) {
        asm volatile("{\n\t.reg .pred p;\n\t"
            "mbarrier.try_wait.parity.acquire.cta.shared::cta.b64 p, [%1], %2, 0x989680;\n\t"
            "selp.b32 %0, 1, 0, p;\n\t}"
            : "=r"(done) : "r"(a), "r"(phase) : "memory");
    }
}
static __device__ __forceinline__ void tc_alloc(uint32_t slot, uint32_t n) {
    asm volatile("tcgen05.alloc.cta_group::1.sync.aligned.shared::cta.b32 [%0], %1;"
                 :: "r"(slot), "r"(n) : "memory");
}
static __device__ __forceinline__ void tc_dealloc(uint32_t t, uint32_t n) {
    asm volatile("tcgen05.dealloc.cta_group::1.sync.aligned.b32 %0, %1;" :: "r"(t), "r"(n));
}
static __device__ __forceinline__ void tc_relinq() {
    asm volatile("tcgen05.relinquish_alloc_permit.cta_group::1.sync.aligned;");
}
static __device__ __forceinline__ void tc_commit(uint32_t mbar) {
    asm volatile("tcgen05.commit.cta_group::1.mbarrier::arrive::one.shared::cluster.b64 [%0];"
                 :: "r"(mbar) : "memory");
}
static __device__ __forceinline__ void tc_fence_after() {
    asm volatile("tcgen05.fence::after_thread_sync;" ::: "memory");
}
static __device__ __forceinline__ void proxy_fence() {
    asm volatile("fence.proxy.async.shared::cta;" ::: "memory");
}
static __device__ __forceinline__ void mma_ss_f16(uint32_t d, uint64_t ad, uint64_t bd,
                                                  uint32_t idesc, uint32_t en) {
    asm volatile("{\n\t.reg .pred p;\n\tsetp.ne.u32 p, %4, 0;\n\t"
        "tcgen05.mma.cta_group::1.kind::f16 [%0], %1, %2, %3, {%5, %5, %5, %5}, p;\n\t}"
        :: "r"(d), "l"(ad), "l"(bd), "r"(idesc), "r"(en), "r"(0u) : "memory");
}
static __device__ __forceinline__ void ldtm32(uint32_t* r, uint32_t a) {
    asm volatile("tcgen05.ld.sync.aligned.32x32b.x32.b32 "
        "{%0,%1,%2,%3,%4,%5,%6,%7,%8,%9,%10,%11,%12,%13,%14,%15,"
        "%16,%17,%18,%19,%20,%21,%22,%23,%24,%25,%26,%27,%28,%29,%30,%31}, [%32];"
        : "=r"(r[0]),"=r"(r[1]),"=r"(r[2]),"=r"(r[3]),"=r"(r[4]),"=r"(r[5]),"=r"(r[6]),"=r"(r[7]),
          "=r"(r[8]),"=r"(r[9]),"=r"(r[10]),"=r"(r[11]),"=r"(r[12]),"=r"(r[13]),"=r"(r[14]),"=r"(r[15]),
          "=r"(r[16]),"=r"(r[17]),"=r"(r[18]),"=r"(r[19]),"=r"(r[20]),"=r"(r[21]),"=r"(r[22]),"=r"(r[23]),
          "=r"(r[24]),"=r"(r[25]),"=r"(r[26]),"=r"(r[27]),"=r"(r[28]),"=r"(r[29]),"=r"(r[30]),"=r"(r[31])
        : "r"(a));
}
static __device__ __forceinline__ void tc_wait_ld() {
    asm volatile("tcgen05.wait::ld.sync.aligned;" ::: "memory");
}
static constexpr uint64_t DESC_BASE =
    (uint64_t(2) << 61) | (uint64_t(1) << 46) | (uint64_t(64) << 32) | (uint64_t(1) << 16);
static __device__ __forceinline__ uint64_t make_desc(uint32_t a) {
    return DESC_BASE | ((uint64_t)(a >> 4) & 0x3FFF);
}
#define GEMM_IDESC ((1u<<4)|(1u<<7)|(1u<<10)|((128u/8)<<17)|((128u/16)<<24))
#endif // TC_OK

// ============================ GEMM kernel ============================
struct Seg { const bf16* A; const bf16* B; int K; };
struct GArgs {
    Seg s[6]; int nseg;
    const float* bias1; const float* bias2;
    const float* c0;      // op==3 (fused lstm cell)
    float* tso;           // op==3 optional float x output
    float* Cf; bf16* Ch; bf16* Cl;
    int ldc; int op;  // 0 none, 1 relu, 2 tanh, 3 lstm-cell (interleaved gates)
};
#define SM_STAGE0 1024
#define SM_STAGEB 32768
#define GEMM_SMEM (1024 + 128 * 129 * 4 + 256)

__global__ __launch_bounds__(256, 2)
void gemm_tc(GArgs args)
{
    extern __shared__ __align__(1024) char smem[];
    const uint32_t sb = smem_u32(smem);
    const int tid = threadIdx.x;
    const int wid = tid >> 5;
    const int lane = tid & 31;
    const int bM = blockIdx.y * 128;
    const int bN = blockIdx.x * 128;

#ifdef TC_OK
    // ======================= tcgen05 path (unused under this toolchain) ===
    if (wid == 0) tc_alloc(sb + 0, 128);
    if (tid == 0) { mbar_init(sb + 16, 1); mbar_init(sb + 24, 1); }
    __syncthreads();
    uint32_t tmem;
    asm volatile("ld.shared.b32 %0, [%1];" : "=r"(tmem) : "r"(sb + 0));

    int c = 0, ph0 = 0, ph1 = 0;
    for (int sg = 0; sg < args.nseg; sg++) {
        const bf16* A = args.s[sg].A;
        const bf16* B = args.s[sg].B;
        const int K = args.s[sg].K;
        for (int k0 = 0; k0 < K; k0 += 64) {
            const int slot = c & 1;
            if (c >= 2) {
                if (slot) { mbar_wait(sb + 24, ph1); ph1 ^= 1; }
                else      { mbar_wait(sb + 16, ph0); ph0 ^= 1; }
            }
            char* stA = smem + SM_STAGE0 + slot * SM_STAGEB;
            char* stB = stA + 16384;
#pragma unroll
            for (int i = 0; i < 4; i++) {
                int idx = tid + i * 256;
                int row = idx >> 3, g = idx & 7;
                uint4 v = *reinterpret_cast<const uint4*>(A + (size_t)(bM + row) * K + k0 + g * 8);
                uint32_t off = (uint32_t)(row * 128 + g * 16);
                off ^= (off >> 3) & 0x70;
                *reinterpret_cast<uint4*>(stA + off) = v;
            }
#pragma unroll
            for (int i = 0; i < 4; i++) {
                int idx = tid + i * 256;
                int row = idx >> 3, g = idx & 7;
                uint4 v = *reinterpret_cast<const uint4*>(B + (size_t)(bN + row) * K + k0 + g * 8);
                uint32_t off = (uint32_t)(row * 128 + g * 16);
                off ^= (off >> 3) & 0x70;
                *reinterpret_cast<uint4*>(stB + off) = v;
            }
            proxy_fence();
            __syncthreads();
            if (wid == 0 && elect_one()) {
                uint64_t ad = make_desc(sb + SM_STAGE0 + slot * SM_STAGEB);
                uint64_t bd = ad + (16384 >> 4);
#pragma unroll
                for (int kk = 0; kk < 4; kk++)
                    mma_ss_f16(tmem, ad + 2 * kk, bd + 2 * kk, GEMM_IDESC,
                               (c > 0 || kk > 0) ? 1u : 0u);
                tc_commit(sb + 16 + slot * 8);
            }
            c++;
        }
    }
    {
        int s0 = c & 1;
        if (s0) { mbar_wait(sb + 24, ph1); ph1 ^= 1; } else { mbar_wait(sb + 16, ph0); ph0 ^= 1; }
        int s1 = (c + 1) & 1;
        if (s1) { mbar_wait(sb + 24, ph1); ph1 ^= 1; } else { mbar_wait(sb + 16, ph0); ph0 ^= 1; }
    }
    tc_fence_after();
    __syncthreads();

    float* epi = reinterpret_cast<float*>(smem + SM_STAGE0);
    if (wid < 4) {
        int row = wid * 32 + lane;
#pragma unroll
        for (int nb = 0; nb < 4; nb++) {
            uint32_t r[32];
            ldtm32(r, tmem + nb * 32);
            tc_wait_ld();
#pragma unroll
            for (int j = 0; j < 32; j++)
                epi[row * 129 + nb * 32 + j] = __uint_as_float(r[j]);
        }
    }
    __syncthreads();

#pragma unroll 1
    for (int it = 0; it < 16; it++) {
        int flat = (it * 256 + tid) * 4;
        int row = flat >> 7, col = flat & 127;
        float v[4];
#pragma unroll
        for (int i = 0; i < 4; i++) {
            float x = epi[row * 129 + col + i];
            if (args.bias1) x += args.bias1[bN + col + i];
            if (args.bias2) x += args.bias2[bN + col + i];
            v[i] = x;
        }
        if (args.op == 3) {
            int h = (bN + col) >> 2;
            int r = bM + row;
            float cc = sigf(v[1]) * args.c0[(size_t)r * HDIM + h] + sigf(v[0]) * tanhf(v[2]);
            float x = sigf(v[3]) * tanhf(cc);
            bf16 hb = __float2bfloat16(x);
            args.Ch[(size_t)r * HDIM + h] = hb;
            args.Cl[(size_t)r * HDIM + h] = __float2bfloat16(x - __bfloat162float(hb));
            if (args.tso) args.tso[(size_t)r * HDIM + h] = x;
            continue;
        }
#pragma unroll
        for (int i = 0; i < 4; i++) {
            if (args.op == 1)      v[i] = fmaxf(v[i], 0.f);
            else if (args.op == 2) v[i] = tanhf(v[i]);
        }
        size_t base = (size_t)(bM + row) * args.ldc + bN + col;
        if (args.Cf)
            *reinterpret_cast<float4*>(args.Cf + base) = make_float4(v[0], v[1], v[2], v[3]);
        if (args.Ch) {
            uint32_t hp[2], lp[2];
#pragma unroll
            for (int h = 0; h < 2; h++) {
                bf16 a = __float2bfloat16(v[2*h]);
                bf16 b = __float2bfloat16(v[2*h+1]);
                bf16 la = __float2bfloat16(v[2*h]   - __bfloat162float(a));
                bf16 lb = __float2bfloat16(v[2*h+1] - __bfloat162float(b));
                hp[h] = (uint32_t)__bfloat16_as_ushort(a) | ((uint32_t)__bfloat16_as_ushort(b) << 16);
                lp[h] = (uint32_t)__bfloat16_as_ushort(la) | ((uint32_t)__bfloat16_as_ushort(lb) << 16);
            }
            *reinterpret_cast<uint2*>(args.Ch + base) = make_uint2(hp[0], hp[1]);
            *reinterpret_cast<uint2*>(args.Cl + base) = make_uint2(lp[0], lp[1]);
        }
    }
    __syncthreads();
    if (wid == 0) { tc_relinq(); tc_dealloc(tmem, 128); }

#else
    // ======================= HMMA mma.sync path (plain sm_103) ===========
    int segBase[7];
    segBase[0] = 0;
#pragma unroll
    for (int i = 0; i < 6; i++)
        segBase[i + 1] = segBase[i] + ((i < args.nseg) ? (args.s[i].K >> 5) : 0);
    const int nch = segBase[6];

    const int wm = (wid >> 1) * 32;
    const int wn = (wid & 1) * 64;

    float ac[2][8][4];
#pragma unroll
    for (int mt = 0; mt < 2; mt++)
#pragma unroll
        for (int nt = 0; nt < 8; nt++)
#pragma unroll
            for (int i = 0; i < 4; i++) ac[mt][nt][i] = 0.f;

    auto loadChunk = [&](int cc) {
        int s = 0;
#pragma unroll
        for (int i = 0; i < 5; i++) if (cc >= segBase[i + 1]) s = i + 1;
        const bf16* A = args.s[s].A;
        const bf16* B = args.s[s].B;
        const int K = args.s[s].K;
        const int k0 = (cc - segBase[s]) * 32;
        uint32_t st = sb + (uint32_t)(cc & 1) * 20480u;
#pragma unroll
        for (int i = 0; i < 2; i++) {
            int ch = tid + i * 256;
            int row = ch >> 2, cb = ch & 3;
            cpa16(st + (uint32_t)(row * 80 + cb * 16),
                  A + (size_t)(bM + row) * K + k0 + cb * 8);
        }
#pragma unroll
        for (int i = 0; i < 2; i++) {
            int ch = tid + i * 256;
            int row = ch >> 2, cb = ch & 3;
            cpa16(st + 10240u + (uint32_t)(row * 80 + cb * 16),
                  B + (size_t)(bN + row) * K + k0 + cb * 8);
        }
    };

    loadChunk(0); cp_commit();
    for (int cc = 0; cc < nch; cc++) {
        const bool more = (cc + 1 < nch);
        if (more) { loadChunk(cc + 1); cp_commit(); }
        if (more) cp_wait1(); else cp_wait0();
        __syncthreads();
        uint32_t stA = sb + (uint32_t)(cc & 1) * 20480u;
        uint32_t stB = stA + 10240u;
#pragma unroll
        for (int kk = 0; kk < 32; kk += 16) {
            uint32_t af[2][4], bfr[4][4];
#pragma unroll
            for (int mt = 0; mt < 2; mt++)
                ldsm4(af[mt], stA + (uint32_t)((wm + mt * 16 + (lane & 15)) * 80
                                               + (kk + (lane >> 4) * 8) * 2));
#pragma unroll
            for (int p = 0; p < 4; p++)
                ldsm4(bfr[p], stB + (uint32_t)((wn + p * 16 + (lane & 7) + ((lane >> 4) & 1) * 8) * 80
                                               + (kk + ((lane >> 3) & 1) * 8) * 2));
#pragma unroll
            for (int mt = 0; mt < 2; mt++)
#pragma unroll
                for (int nt = 0; nt < 8; nt++)
                    mma16816(ac[mt][nt], af[mt], &bfr[nt >> 1][(nt & 1) * 2]);
        }
        __syncthreads();
    }

    if (args.op == 3) {
        // fused LSTM cell: interleaved gate columns 4h+{i,f,g,o}
#pragma unroll
        for (int mt = 0; mt < 2; mt++)
#pragma unroll
            for (int nt = 0; nt < 8; nt++) {
                int row = bM + wm + mt * 16 + (lane >> 2);
                int col = bN + wn + nt * 8 + 2 * (lane & 3);
                float v0 = ac[mt][nt][0] + args.bias1[col];
                float v1 = ac[mt][nt][1] + args.bias1[col + 1];
                float v2 = ac[mt][nt][2] + args.bias1[col];
                float v3 = ac[mt][nt][3] + args.bias1[col + 1];
                float p0 = __shfl_xor_sync(0xffffffffu, v0, 1);
                float p1 = __shfl_xor_sync(0xffffffffu, v1, 1);
                float p2 = __shfl_xor_sync(0xffffffffu, v2, 1);
                float p3 = __shfl_xor_sync(0xffffffffu, v3, 1);
                if (!(lane & 1)) {
                    int h = col >> 2;
                    float c1 = args.c0[(size_t)row * HDIM + h];
                    float c2 = args.c0[(size_t)(row + 8) * HDIM + h];
                    float cc1 = sigf(v1) * c1 + sigf(v0) * tanhf(p0);
                    float x1 = sigf(p1) * tanhf(cc1);
                    float cc2 = sigf(v3) * c2 + sigf(v2) * tanhf(p2);
                    float x2 = sigf(p3) * tanhf(cc2);
                    bf16 h1 = __float2bfloat16(x1);
                    bf16 h2 = __float2bfloat16(x2);
                    size_t i1 = (size_t)row * HDIM + h;
                    size_t i2 = (size_t)(row + 8) * HDIM + h;
                    args.Ch[i1] = h1;
                    args.Cl[i1] = __float2bfloat16(x1 - __bfloat162float(h1));
                    args.Ch[i2] = h2;
                    args.Cl[i2] = __float2bfloat16(x2 - __bfloat162float(h2));
                    if (args.tso) { args.tso[i1] = x1; args.tso[i2] = x2; }
                }
            }
        return;
    }

    auto storePair = [&](int row, int col, float v0, float v1) {
        if (args.bias1) { v0 += args.bias1[col]; v1 += args.bias1[col + 1]; }
        if (args.bias2) { v0 += args.bias2[col]; v1 += args.bias2[col + 1]; }
        if (args.op == 1)      { v0 = fmaxf(v0, 0.f); v1 = fmaxf(v1, 0.f); }
        else if (args.op == 2) { v0 = tanhf(v0); v1 = tanhf(v1); }
        size_t base = (size_t)row * args.ldc + col;
        if (args.Cf)
            *reinterpret_cast<float2*>(args.Cf + base) = make_float2(v0, v1);
        if (args.Ch) {
            bf16 h0 = __float2bfloat16(v0), h1 = __float2bfloat16(v1);
            bf16 l0 = __float2bfloat16(v0 - __bfloat162float(h0));
            bf16 l1 = __float2bfloat16(v1 - __bfloat162float(h1));
            *reinterpret_cast<uint32_t*>(args.Ch + base) =
                (uint32_t)__bfloat16_as_ushort(h0) | ((uint32_t)__bfloat16_as_ushort(h1) << 16);
            *reinterpret_cast<uint32_t*>(args.Cl + base) =
                (uint32_t)__bfloat16_as_ushort(l0) | ((uint32_t)__bfloat16_as_ushort(l1) << 16);
        }
    };
#pragma unroll
    for (int mt = 0; mt < 2; mt++)
#pragma unroll
        for (int nt = 0; nt < 8; nt++) {
            int row = bM + wm + mt * 16 + (lane >> 2);
            int col = bN + wn + nt * 8 + 2 * (lane & 3);
            storePair(row,     col, ac[mt][nt][0], ac[mt][nt][1]);
            storePair(row + 8, col, ac[mt][nt][2], ac[mt][nt][3]);
        }
#endif
}

// ============================ conversion ============================
// permBlock>0: within each permBlock-row block, dst row r maps to src row (r&3)*512 + (r>>2)
__global__ void conv_hl(const float* __restrict__ src, int rows, int Ks, int ld, int Kd,
                        bf16* __restrict__ h, bf16* __restrict__ l,
                        const float* __restrict__ divr, int permBlock)
{
    int idx = blockIdx.x * blockDim.x + threadIdx.x;
    if (idx >= rows * Kd) return;
    int r = idx / Kd, k = idx - r * Kd;
    int sr = r;
    if (permBlock) {
        int blk = r / permBlock, rr = r - blk * permBlock;
        sr = blk * permBlock + (rr & 3) * 512 + (rr >> 2);
    }
    float v = (k < Ks) ? src[(size_t)sr * ld + k] : 0.f;
    if (divr) v /= divr[r];
    bf16 hb = __float2bfloat16(v);
    h[idx] = hb;
    l[idx] = __float2bfloat16(v - __bfloat162float(hb));
}

// permuted combined bias: biasp[l][4h+g] = b_ih[l][g*512+h] + b_hh[l][g*512+h]
__global__ void biasp_kernel(const float* __restrict__ b_ih, const float* __restrict__ b_hh,
                             float* __restrict__ bp)
{
    int idx = blockIdx.x * blockDim.x + threadIdx.x;
    if (idx >= NL * G4) return;
    int l = idx >> 11, rr = idx & 2047;
    int sr = (rr & 3) * 512 + (rr >> 2);
    bp[idx] = b_ih[l * G4 + sr] + b_hh[l * G4 + sr];
}

__global__ void raw_dnn_kernel(const float* __restrict__ z, const float* __restrict__ W2,
                               const float* __restrict__ b2, const float* __restrict__ rng,
                               const void* __restrict__ scale_ptr,
                               float* __restrict__ raw_out, float* __restrict__ dnn_out)
{
    __shared__ float zs[2 * HDIM];
    int b = blockIdx.x;
    const float* zr = z + (size_t)b * 2 * HDIM;
    for (int i = threadIdx.x; i < 2 * HDIM; i += blockDim.x) zs[i] = zr[i];
    __syncthreads();
    int warp = threadIdx.x >> 5, lane = threadIdx.x & 31;
    int bits = *(const int*)scale_ptr;
    float f = __int_as_float(bits);
    float af = fabsf(f);
    float s = (af >= 1e-30f && af <= 1e30f) ? f : (float)bits;
    for (int o = warp; o < OUTD; o += 8) {
        const float* w = W2 + (size_t)o * 2 * HDIM;
        float acc = 0.f;
        for (int k = lane; k < 2 * HDIM; k += 32) acc += zs[k] * w[k];
#pragma unroll
        for (int off = 16; off; off >>= 1) acc += __shfl_xor_sync(0xffffffffu, acc, off);
        if (lane == 0) {
            float r = acc + b2[o];
            raw_out[(size_t)b * OUTD + o] = r;
            dnn_out[(size_t)b * OUTD + o] = (1.f / (1.f + expf(-r * s))) * rng[o];
        }
    }
}

// ============================ ODE ============================
#define LN2D 0.6931471805599453
#define C_RI  ((float)(LN2D / 5.0))
#define C_RD  ((float)(LN2D / 2.0))
#define C_RRI ((float)(LN2D / 10.0))
#define C_RRH ((float)(LN2D / 15.0))
#define C_RRV ((float)(LN2D / 10.0))
#define TWO_OVER_PI 0.6366197723675814f
#define HALF_PI     1.5707963267948966f

__device__ __forceinline__ void covid_deriv(const float y[16], float gam, float pdt,
                                            float aN, float r_dth, float d[16])
{
    float S = y[0], E = y[1], I = y[2];
    float AR = y[3], DHR = y[4], DQR = y[5], AD = y[6], DHD = y[7], DQD = y[8];
    float DVR = y[12], DVD = y[13];
    float inf = aN * gam * S * I;
    float det = C_RD * I;
    float d1m = det * (1.f - pdt);
    float dp  = det * pdt;
    d[0] = -inf;
    d[1] = inf - C_RI * E;
    d[2] = C_RI * E - det;
    d[3] = d1m * 0.8f - C_RRI * AR;
    d[4] = d1m * 0.03f - C_RRH * DHR;
    d[5] = d1m * 0.17f - C_RRI * DQR;
    d[6] = dp * 0.8f - r_dth * AD;
    d[7] = dp * 0.03f - r_dth * DHD;
    d[8] = dp * 0.17f - r_dth * DQD;
    d[9] = C_RRI * (AR + DQR) + C_RRH * DHR;
    d[10] = r_dth * (AD + DQD + DHD);
    d[11] = det * 0.03f;
    d[12] = d1m * 0.0075f - C_RRV * DVR;
    d[13] = dp * 0.0075f - r_dth * DVD;
    d[14] = r_dth * (DHD + DQD);
    d[15] = det * 0.2f;
}
__device__ __forceinline__ float gam_f(float t, float days, float rs20,
                                       float jump, float t_jump, float inv2s2)
{
    float dtj = t - t_jump;
    return TWO_OVER_PI * atanf((days - t) * rs20) + 1.0f + jump * __expf(-dtj * dtj * inv2s2);
}
__device__ __forceinline__ float pdt_f(float t, float pc, float rdd20)
{
    return pc * (atanf(-t * rdd20) + HALF_PI) + 0.001f;
}

__global__ void ode_kernel(const float* __restrict__ pop, const float* __restrict__ ccn,
                           const float* __restrict__ mort, const float* __restrict__ dnn,
                           float* __restrict__ sol)
{
    int b = blockIdx.x * blockDim.x + threadIdx.x;
    if (b >= BATCH) return;
    const float* dn = dnn + (size_t)b * OUTD;
    float alpha = dn[11], days = dn[12], r_s = dn[13], r_dth = dn[14], p_dth = dn[15];
    float r_dthdecay = dn[16], k1 = dn[17], k2 = dn[18], jump = dn[19];
    float t_jump = dn[20], stdn = dn[21];

    float N = pop[b];
    float PopI = ccn[b];
    float PopD = floorf(mort[b] * PopI);
    float R0 = (PopI - PopD > 5.0f * PopD) ? 5.0f * PopD : 0.0f;
    float PopCI = PopI - PopD - R0;
    float ciPD = PopCI / 0.2f;
    float omp = 1.0f - p_dth;

    float y[16];
    y[0] = N - ciPD * (k1 + k2) - R0 / 0.2f - PopD / 0.2f;
    y[1] = ciPD * k1;  y[2] = ciPD * k2;
    y[3] = (ciPD - PopCI) * omp;
    y[4] = PopCI * 0.15f * omp;
    y[5] = PopCI * 0.85f * omp;
    y[6] = (ciPD - PopCI) * p_dth;
    y[7] = PopCI * 0.15f * p_dth;
    y[8] = PopCI * 0.85f * p_dth;
    y[9] = R0 / 0.2f;  y[10] = PopD / 0.2f;
    y[11] = PopCI * 0.15f;
    y[12] = PopCI * 0.0375f * omp;
    y[13] = PopCI * 0.0375f * p_dth;
    y[14] = PopD;  y[15] = PopI;

    float* srow = sol + (size_t)b * TPTS * 16;
#pragma unroll
    for (int i = 0; i < 16; i++) srow[i] = y[i];

    float aN = alpha / N;
    float rs20 = r_s * 0.05f;
    float rdd20 = r_dthdecay * 0.05f;
    float inv2s2 = 1.0f / (2.0f * stdn * stdn);
    float pc = TWO_OVER_PI * (p_dth - 0.001f);

    for (int seg = 0; seg < TPTS - 1; seg++) {
        float t0 = (float)seg;
        for (int j = 0; j < 10; j++) {
            float t = t0 + (float)j * 0.1f;
            float g1 = gam_f(t, days, rs20, jump, t_jump, inv2s2);
            float g2 = gam_f(t + 0.05f, days, rs20, jump, t_jump, inv2s2);
            float g3 = gam_f(t + 0.1f, days, rs20, jump, t_jump, inv2s2);
            float p1 = pdt_f(t, pc, rdd20);
            float p2 = pdt_f(t + 0.05f, pc, rdd20);
            float p3 = pdt_f(t + 0.1f, pc, rdd20);
            float k[16], acc[16], yy[16];
            covid_deriv(y, g1, p1, aN, r_dth, k);
#pragma unroll
            for (int i = 0; i < 16; i++) { acc[i] = k[i]; yy[i] = y[i] + 0.05f * k[i]; }
            covid_deriv(yy, g2, p2, aN, r_dth, k);
#pragma unroll
            for (int i = 0; i < 16; i++) { acc[i] += 2.f * k[i]; yy[i] = y[i] + 0.05f * k[i]; }
            covid_deriv(yy, g2, p2, aN, r_dth, k);
#pragma unroll
            for (int i = 0; i < 16; i++) { acc[i] += 2.f * k[i]; yy[i] = y[i] + 0.1f * k[i]; }
            covid_deriv(yy, g3, p3, aN, r_dth, k);
#pragma unroll
            for (int i = 0; i < 16; i++) y[i] += (0.1f / 6.0f) * (acc[i] + k[i]);
        }
        float* o = srow + (size_t)(seg + 1) * 16;
#pragma unroll
        for (int i = 0; i < 16; i++) o[i] = y[i];
    }
}

// ============================ launch ============================
static void* sym(const void* s) { void* p; cudaGetSymbolAddress(&p, s); return p; }

extern "C" void kernel_launch(void* const* d_in, const int* in_sizes, int n_in,
                              void* d_out, int out_size)
{
    const float* mi    = (const float*)d_in[0];
    const float* pop   = (const float*)d_in[1];
    const float* ccn   = (const float*)d_in[2];
    const float* mort  = (const float*)d_in[3];
    const float* h0    = (const float*)d_in[4];
    const float* c0    = (const float*)d_in[5];
    const float* W_ih0 = (const float*)d_in[6];
    const float* W_ihR = (const float*)d_in[7];
    const float* W_hh  = (const float*)d_in[8];
    const float* b_ih  = (const float*)d_in[9];
    const float* b_hh  = (const float*)d_in[10];
    const float* mW1   = (const float*)d_in[11];
    const float* mb1   = (const float*)d_in[12];
    const float* mW2   = (const float*)d_in[13];
    const float* mb2   = (const float*)d_in[14];
    const float* rW1   = (const float*)d_in[15];
    const float* rb1   = (const float*)d_in[16];
    const float* rW2   = (const float*)d_in[17];
    const float* rb2   = (const float*)d_in[18];
    const float* rng   = (const float*)d_in[19];
    const void*  scl   = d_in[20];

    float* out = (float*)d_out;
    float* sol = out;
    float* dnn = out + (size_t)BATCH * TPTS * 16;
    float* ts  = dnn + (size_t)BATCH * OUTD;
    float* raw = ts  + (size_t)BATCH * HDIM;

    float* zb    = (float*)sym(g_z);
    float* biasp = (float*)sym(g_biasp);
    bf16 *x30h = (bf16*)sym(g_x30h), *x30l = (bf16*)sym(g_x30l);
    bf16 *mih  = (bf16*)sym(g_mih),  *mil  = (bf16*)sym(g_mil);
    bf16 *wi0h = (bf16*)sym(g_wi0h), *wi0l = (bf16*)sym(g_wi0l);
    bf16 *wirh = (bf16*)sym(g_wirh), *wirl = (bf16*)sym(g_wirl);
    bf16 *whhh = (bf16*)sym(g_whhh), *whhl = (bf16*)sym(g_whhl);
    bf16 *h0h  = (bf16*)sym(g_h0h),  *h0l  = (bf16*)sym(g_h0l);
    bf16 *mw1h = (bf16*)sym(g_mw1h), *mw1l = (bf16*)sym(g_mw1l);
    bf16 *mw2h = (bf16*)sym(g_mw2h), *mw2l = (bf16*)sym(g_mw2l);
    bf16 *r1ah = (bf16*)sym(g_r1ah), *r1al = (bf16*)sym(g_r1al);
    bf16 *r1bh = (bf16*)sym(g_r1bh), *r1bl = (bf16*)sym(g_r1bl);
    bf16 *xAh  = (bf16*)sym(g_xAh),  *xAl  = (bf16*)sym(g_xAl);
    bf16 *xBh  = (bf16*)sym(g_xBh),  *xBl  = (bf16*)sym(g_xBl);
    bf16 *m1h  = (bf16*)sym(g_m1h),  *m1l  = (bf16*)sym(g_m1l);
    bf16 *m2h  = (bf16*)sym(g_m2h),  *m2l  = (bf16*)sym(g_m2l);

    static cudaStream_t s1 = nullptr;
    static cudaEvent_t  evF = nullptr, evJ = nullptr;
    if (!s1) {
        cudaStreamCreateWithFlags(&s1, cudaStreamNonBlocking);
        cudaEventCreateWithFlags(&evF, cudaEventDisableTiming);
        cudaEventCreateWithFlags(&evJ, cudaEventDisableTiming);
        cudaFuncSetAttribute(gemm_tc, cudaFuncAttributeMaxDynamicSharedMemorySize, GEMM_SMEM);
    }

    auto CV = [&](cudaStream_t st, const float* s, int rows, int Ks, int ld, int Kd,
                  bf16* h, bf16* l, const float* dv, int perm) {
        int n = rows * Kd;
        conv_hl<<<(n + 255) / 256, 256, 0, st>>>(s, rows, Ks, ld, Kd, h, l, dv, perm);
    };
    auto GL = [&](cudaStream_t st, dim3 grid, Seg* sg, int ns, const float* b1, const float* b2,
                  const float* c0p, float* tso,
                  float* Cf, bf16* Ch, bf16* Cl, int ldc, int op) {
        GArgs a = {};
        for (int i = 0; i < ns; i++) a.s[i] = sg[i];
        a.nseg = ns; a.bias1 = b1; a.bias2 = b2; a.c0 = c0p; a.tso = tso;
        a.Cf = Cf; a.Ch = Ch; a.Cl = Cl; a.ldc = ldc; a.op = op;
        gemm_tc<<<grid, 256, GEMM_SMEM, st>>>(a);
    };

    // fork: meta/readout prep on s1
    cudaEventRecord(evF, 0);
    cudaStreamWaitEvent(s1, evF, 0);

    // ---- default stream: LSTM-critical conversions ----
    CV(0, mi,    BATCH,     TTL,  IN_DIM, 64,   x30h, x30l, pop,     0);
    CV(0, W_ih0, G4,        TTL,  TTL,    64,   wi0h, wi0l, nullptr, 2048);
    CV(0, W_ihR, 4 * G4,    HDIM, HDIM,   HDIM, wirh, wirl, nullptr, 2048);
    CV(0, W_hh,  5 * G4,    HDIM, HDIM,   HDIM, whhh, whhl, nullptr, 2048);
    CV(0, h0,    5 * BATCH, HDIM, HDIM,   HDIM, h0h,  h0l,  nullptr, 0);
    biasp_kernel<<<(NL * G4 + 255) / 256, 256>>>(b_ih, b_hh, biasp);

    // ---- s1: meta branch + readout weights ----
    CV(s1, mi + TTL,   BATCH,    30,   IN_DIM, 64,   mih,  mil,  nullptr, 0);
    CV(s1, mW1,        HDIM,     30,   30,     64,   mw1h, mw1l, nullptr, 0);
    CV(s1, mW2,        HDIM,     HDIM, HDIM,   HDIM, mw2h, mw2l, nullptr, 0);
    CV(s1, rW1,        2 * HDIM, HDIM, 2*HDIM, HDIM, r1ah, r1al, nullptr, 0);
    CV(s1, rW1 + HDIM, 2 * HDIM, HDIM, 2*HDIM, HDIM, r1bh, r1bl, nullptr, 0);
    dim3 mGrid(HDIM / 128, BATCH / 128);
    { Seg sg[3] = { {mih, mw1h, 64}, {mil, mw1h, 64}, {mih, mw1l, 64} };
      GL(s1, mGrid, sg, 3, mb1, nullptr, nullptr, nullptr, nullptr, m1h, m1l, HDIM, 1); }
    { Seg sg[3] = { {m1h, mw2h, HDIM}, {m1l, mw2h, HDIM}, {m1h, mw2l, HDIM} };
      GL(s1, mGrid, sg, 3, mb2, nullptr, nullptr, nullptr, nullptr, m2h, m2l, HDIM, 1); }
    cudaEventRecord(evJ, s1);

    // ---- default stream: LSTM chain, fused cell epilogue, ping-pong x ----
    dim3 gGrid(G4 / 128, BATCH / 128);
    for (int l = 0; l < NL; l++) {
        bf16* ah = (l == 0) ? x30h : ((l & 1) ? xAh : xBh);
        bf16* al = (l == 0) ? x30l : ((l & 1) ? xAl : xBl);
        bf16* oh = (l & 1) ? xBh : xAh;   // write the OTHER buffer
        bf16* ol = (l & 1) ? xBl : xAl;
        int   Kx = l ? HDIM : 64;
        bf16* wh = l ? (wirh + (size_t)(l - 1) * G4 * HDIM) : wi0h;
        bf16* wl = l ? (wirl + (size_t)(l - 1) * G4 * HDIM) : wi0l;
        bf16* hh = h0h + (size_t)l * BATCH * HDIM;
        bf16* hl = h0l + (size_t)l * BATCH * HDIM;
        bf16* Wh = whhh + (size_t)l * G4 * HDIM;
        bf16* Wl = whhl + (size_t)l * G4 * HDIM;
        Seg sg[6] = { {ah, wh, Kx}, {al, wh, Kx}, {ah, wl, Kx},
                      {hh, Wh, HDIM}, {hl, Wh, HDIM}, {hh, Wl, HDIM} };
        GL(0, gGrid, sg, 6, biasp + (size_t)l * G4, nullptr,
           c0 + (size_t)l * BATCH * HDIM, (l == NL - 1) ? ts : nullptr,
           nullptr, oh, ol, HDIM, 3);
    }
    // layer 4 (l=4, even) wrote buffer A
    bf16* xfh = xAh;
    bf16* xfl = xAl;

    // join meta branch, then readout
    cudaStreamWaitEvent(0, evJ, 0);
    dim3 zGrid(2 * HDIM / 128, BATCH / 128);
    { Seg sg[6] = { {xfh, r1ah, HDIM}, {xfl, r1ah, HDIM}, {xfh, r1al, HDIM},
                    {m2h, r1bh, HDIM}, {m2l, r1bh, HDIM}, {m2h, r1bl, HDIM} };
      GL(0, zGrid, sg, 6, rb1, nullptr, nullptr, nullptr, zb, nullptr, nullptr, 2 * HDIM, 2); }

    raw_dnn_kernel<<<BATCH, 256>>>(zb, rW2, rb2, rng, scl, raw, dnn);
    ode_kernel<<<(BATCH + 63) / 64, 64>>>(pop, ccn, mort, dnn, sol);
}

// round 9
// speedup vs baseline: 1.8611x; 1.0185x over previous
#include <cuda_runtime.h>
#include <cuda_bf16.h>
#include <math.h>
#include <stdint.h>

typedef __nv_bfloat16 bf16;

#define BATCH 2048
#define TTL   30
#define IN_DIM 60
#define HDIM  512
#define G4    2048
#define NL    5
#define OUTD  23
#define TPTS  90

#if !defined(__CUDA_ARCH__) || defined(__CUDA_ARCH_FEAT_SM103_ALL) || defined(__CUDA_ARCH_FEAT_SM100_ALL)
#define TC_OK 1
#endif

// ============================ static scratch ============================
__device__ float g_z    [BATCH * 2 * HDIM];
__device__ float g_biasp[NL * G4];
__device__ bf16  g_x30h[BATCH * 64],  g_x30l[BATCH * 64];
__device__ bf16  g_mih [BATCH * 64],  g_mil [BATCH * 64];
__device__ bf16  g_wi0h[G4 * 64],     g_wi0l[G4 * 64];
__device__ bf16  g_wirh[4 * G4 * HDIM], g_wirl[4 * G4 * HDIM];
__device__ bf16  g_whhh[5 * G4 * HDIM], g_whhl[5 * G4 * HDIM];
__device__ bf16  g_h0h [5 * BATCH * HDIM], g_h0l[5 * BATCH * HDIM];
__device__ bf16  g_mw1h[HDIM * 64],   g_mw1l[HDIM * 64];
__device__ bf16  g_mw2h[HDIM * HDIM], g_mw2l[HDIM * HDIM];
__device__ bf16  g_r1ah[2 * HDIM * HDIM], g_r1al[2 * HDIM * HDIM];
__device__ bf16  g_r1bh[2 * HDIM * HDIM], g_r1bl[2 * HDIM * HDIM];
// ping-pong x buffers (avoids in-place read/write race in fused LSTM layers)
__device__ bf16  g_xAh [BATCH * HDIM], g_xAl[BATCH * HDIM];
__device__ bf16  g_xBh [BATCH * HDIM], g_xBl[BATCH * HDIM];
__device__ bf16  g_m1h [BATCH * HDIM], g_m1l[BATCH * HDIM];
__device__ bf16  g_m2h [BATCH * HDIM], g_m2l[BATCH * HDIM];

// ============================ common helpers ============================
static __device__ __forceinline__ uint32_t smem_u32(const void* p) {
    uint32_t a;
    asm("{ .reg .u64 t; cvta.to.shared.u64 t, %1; cvt.u32.u64 %0, t; }" : "=r"(a) : "l"(p));
    return a;
}
static __device__ __forceinline__ void cpa16(uint32_t d, const void* s) {
    asm volatile("cp.async.cg.shared.global [%0], [%1], 16;" :: "r"(d), "l"(s));
}
static __device__ __forceinline__ void cp_commit() {
    asm volatile("cp.async.commit_group;" ::: "memory");
}
static __device__ __forceinline__ void cp_wait0() {
    asm volatile("cp.async.wait_group 0;" ::: "memory");
}
static __device__ __forceinline__ void cp_wait1() {
    asm volatile("cp.async.wait_group 1;" ::: "memory");
}
static __device__ __forceinline__ void ldsm4(uint32_t* r, uint32_t a) {
    asm volatile("ldmatrix.sync.aligned.m8n8.x4.shared.b16 {%0,%1,%2,%3}, [%4];"
                 : "=r"(r[0]), "=r"(r[1]), "=r"(r[2]), "=r"(r[3]) : "r"(a));
}
static __device__ __forceinline__ void mma16816(float* c, const uint32_t* a, const uint32_t* b) {
    asm volatile("mma.sync.aligned.m16n8k16.row.col.f32.bf16.bf16.f32 "
                 "{%0,%1,%2,%3}, {%4,%5,%6,%7}, {%8,%9}, {%0,%1,%2,%3};"
                 : "+f"(c[0]), "+f"(c[1]), "+f"(c[2]), "+f"(c[3])
                 : "r"(a[0]), "r"(a[1]), "r"(a[2]), "r"(a[3]), "r"(b[0]), "r"(b[1]));
}
static __device__ __forceinline__ float sigf(float x) { return 1.f / (1.f + expf(-x)); }

#ifdef TC_OK
static __device__ __forceinline__ uint32_t elect_one() {
    uint32_t p;
    asm volatile("{ .reg .pred p; elect.sync _|p, 0xFFFFFFFF; selp.b32 %0, 1, 0, p; }" : "=r"(p));
    return p;
}
static __device__ __forceinline__ void mbar_init(uint32_t a, uint32_t cnt) {
    asm volatile("mbarrier.init.shared.b64 [%0], %1;" :: "r"(a), "r"(cnt) : "memory");
}
static __device__ __forceinline__ void mbar_wait(uint32_t a, uint32_t phase) {
    uint32_t done = 0;
    while (!done) {
        asm volatile("{\n\t.reg .pred p;\n\t"
            "mbarrier.try_wait.parity.acquire.cta.shared::cta.b64 p, [%1], %2, 0x989680;\n\t"
            "selp.b32 %0, 1, 0, p;\n\t}"
            : "=r"(done) : "r"(a), "r"(phase) : "memory");
    }
}
static __device__ __forceinline__ void tc_alloc(uint32_t slot, uint32_t n) {
    asm volatile("tcgen05.alloc.cta_group::1.sync.aligned.shared::cta.b32 [%0], %1;"
                 :: "r"(slot), "r"(n) : "memory");
}
static __device__ __forceinline__ void tc_dealloc(uint32_t t, uint32_t n) {
    asm volatile("tcgen05.dealloc.cta_group::1.sync.aligned.b32 %0, %1;" :: "r"(t), "r"(n));
}
static __device__ __forceinline__ void tc_relinq() {
    asm volatile("tcgen05.relinquish_alloc_permit.cta_group::1.sync.aligned;");
}
static __device__ __forceinline__ void tc_commit(uint32_t mbar) {
    asm volatile("tcgen05.commit.cta_group::1.mbarrier::arrive::one.shared::cluster.b64 [%0];"
                 :: "r"(mbar) : "memory");
}
static __device__ __forceinline__ void tc_fence_after() {
    asm volatile("tcgen05.fence::after_thread_sync;" ::: "memory");
}
static __device__ __forceinline__ void proxy_fence() {
    asm volatile("fence.proxy.async.shared::cta;" ::: "memory");
}
static __device__ __forceinline__ void mma_ss_f16(uint32_t d, uint64_t ad, uint64_t bd,
                                                  uint32_t idesc, uint32_t en) {
    asm volatile("{\n\t.reg .pred p;\n\tsetp.ne.u32 p, %4, 0;\n\t"
        "tcgen05.mma.cta_group::1.kind::f16 [%0], %1, %2, %3, {%5, %5, %5, %5}, p;\n\t}"
        :: "r"(d), "l"(ad), "l"(bd), "r"(idesc), "r"(en), "r"(0u) : "memory");
}
static __device__ __forceinline__ void ldtm32(uint32_t* r, uint32_t a) {
    asm volatile("tcgen05.ld.sync.aligned.32x32b.x32.b32 "
        "{%0,%1,%2,%3,%4,%5,%6,%7,%8,%9,%10,%11,%12,%13,%14,%15,"
        "%16,%17,%18,%19,%20,%21,%22,%23,%24,%25,%26,%27,%28,%29,%30,%31}, [%32];"
        : "=r"(r[0]),"=r"(r[1]),"=r"(r[2]),"=r"(r[3]),"=r"(r[4]),"=r"(r[5]),"=r"(r[6]),"=r"(r[7]),
          "=r"(r[8]),"=r"(r[9]),"=r"(r[10]),"=r"(r[11]),"=r"(r[12]),"=r"(r[13]),"=r"(r[14]),"=r"(r[15]),
          "=r"(r[16]),"=r"(r[17]),"=r"(r[18]),"=r"(r[19]),"=r"(r[20]),"=r"(r[21]),"=r"(r[22]),"=r"(r[23]),
          "=r"(r[24]),"=r"(r[25]),"=r"(r[26]),"=r"(r[27]),"=r"(r[28]),"=r"(r[29]),"=r"(r[30]),"=r"(r[31])
        : "r"(a));
}
static __device__ __forceinline__ void tc_wait_ld() {
    asm volatile("tcgen05.wait::ld.sync.aligned;" ::: "memory");
}
static constexpr uint64_t DESC_BASE =
    (uint64_t(2) << 61) | (uint64_t(1) << 46) | (uint64_t(64) << 32) | (uint64_t(1) << 16);
static __device__ __forceinline__ uint64_t make_desc(uint32_t a) {
    return DESC_BASE | ((uint64_t)(a >> 4) & 0x3FFF);
}
#define GEMM_IDESC ((1u<<4)|(1u<<7)|(1u<<10)|((128u/8)<<17)|((128u/16)<<24))
#endif // TC_OK

// ============================ GEMM kernel ============================
struct Seg { const bf16* A; const bf16* B; int K; };
struct GArgs {
    Seg s[6]; int nseg;
    const float* bias1; const float* bias2;
    const float* c0;      // op==3 (fused lstm cell)
    float* tso;           // op==3 optional float x output
    float* Cf; bf16* Ch; bf16* Cl;
    int ldc; int op;  // 0 none, 1 relu, 2 tanh, 3 lstm-cell (interleaved gates)
};
#define SM_STAGE0 1024
#define SM_STAGEB 32768
#define GEMM_SMEM (1024 + 128 * 129 * 4 + 256)

__global__ __launch_bounds__(256, 2)
void gemm_tc(GArgs args)
{
    extern __shared__ __align__(1024) char smem[];
    const uint32_t sb = smem_u32(smem);
    const int tid = threadIdx.x;
    const int wid = tid >> 5;
    const int lane = tid & 31;
    const int bM = blockIdx.y * 128;
    const int bN = blockIdx.x * 128;

#ifdef TC_OK
    // ======================= tcgen05 path (unused under this toolchain) ===
    if (wid == 0) tc_alloc(sb + 0, 128);
    if (tid == 0) { mbar_init(sb + 16, 1); mbar_init(sb + 24, 1); }
    __syncthreads();
    uint32_t tmem;
    asm volatile("ld.shared.b32 %0, [%1];" : "=r"(tmem) : "r"(sb + 0));

    int c = 0, ph0 = 0, ph1 = 0;
    for (int sg = 0; sg < args.nseg; sg++) {
        const bf16* A = args.s[sg].A;
        const bf16* B = args.s[sg].B;
        const int K = args.s[sg].K;
        for (int k0 = 0; k0 < K; k0 += 64) {
            const int slot = c & 1;
            if (c >= 2) {
                if (slot) { mbar_wait(sb + 24, ph1); ph1 ^= 1; }
                else      { mbar_wait(sb + 16, ph0); ph0 ^= 1; }
            }
            char* stA = smem + SM_STAGE0 + slot * SM_STAGEB;
            char* stB = stA + 16384;
#pragma unroll
            for (int i = 0; i < 4; i++) {
                int idx = tid + i * 256;
                int row = idx >> 3, g = idx & 7;
                uint4 v = *reinterpret_cast<const uint4*>(A + (size_t)(bM + row) * K + k0 + g * 8);
                uint32_t off = (uint32_t)(row * 128 + g * 16);
                off ^= (off >> 3) & 0x70;
                *reinterpret_cast<uint4*>(stA + off) = v;
            }
#pragma unroll
            for (int i = 0; i < 4; i++) {
                int idx = tid + i * 256;
                int row = idx >> 3, g = idx & 7;
                uint4 v = *reinterpret_cast<const uint4*>(B + (size_t)(bN + row) * K + k0 + g * 8);
                uint32_t off = (uint32_t)(row * 128 + g * 16);
                off ^= (off >> 3) & 0x70;
                *reinterpret_cast<uint4*>(stB + off) = v;
            }
            proxy_fence();
            __syncthreads();
            if (wid == 0 && elect_one()) {
                uint64_t ad = make_desc(sb + SM_STAGE0 + slot * SM_STAGEB);
                uint64_t bd = ad + (16384 >> 4);
#pragma unroll
                for (int kk = 0; kk < 4; kk++)
                    mma_ss_f16(tmem, ad + 2 * kk, bd + 2 * kk, GEMM_IDESC,
                               (c > 0 || kk > 0) ? 1u : 0u);
                tc_commit(sb + 16 + slot * 8);
            }
            c++;
        }
    }
    {
        int s0 = c & 1;
        if (s0) { mbar_wait(sb + 24, ph1); ph1 ^= 1; } else { mbar_wait(sb + 16, ph0); ph0 ^= 1; }
        int s1 = (c + 1) & 1;
        if (s1) { mbar_wait(sb + 24, ph1); ph1 ^= 1; } else { mbar_wait(sb + 16, ph0); ph0 ^= 1; }
    }
    tc_fence_after();
    __syncthreads();

    float* epi = reinterpret_cast<float*>(smem + SM_STAGE0);
    if (wid < 4) {
        int row = wid * 32 + lane;
#pragma unroll
        for (int nb = 0; nb < 4; nb++) {
            uint32_t r[32];
            ldtm32(r, tmem + nb * 32);
            tc_wait_ld();
#pragma unroll
            for (int j = 0; j < 32; j++)
                epi[row * 129 + nb * 32 + j] = __uint_as_float(r[j]);
        }
    }
    __syncthreads();

#pragma unroll 1
    for (int it = 0; it < 16; it++) {
        int flat = (it * 256 + tid) * 4;
        int row = flat >> 7, col = flat & 127;
        float v[4];
#pragma unroll
        for (int i = 0; i < 4; i++) {
            float x = epi[row * 129 + col + i];
            if (args.bias1) x += args.bias1[bN + col + i];
            if (args.bias2) x += args.bias2[bN + col + i];
            v[i] = x;
        }
        if (args.op == 3) {
            int h = (bN + col) >> 2;
            int r = bM + row;
            float cc = sigf(v[1]) * args.c0[(size_t)r * HDIM + h] + sigf(v[0]) * tanhf(v[2]);
            float x = sigf(v[3]) * tanhf(cc);
            bf16 hb = __float2bfloat16(x);
            args.Ch[(size_t)r * HDIM + h] = hb;
            args.Cl[(size_t)r * HDIM + h] = __float2bfloat16(x - __bfloat162float(hb));
            if (args.tso) args.tso[(size_t)r * HDIM + h] = x;
            continue;
        }
#pragma unroll
        for (int i = 0; i < 4; i++) {
            if (args.op == 1)      v[i] = fmaxf(v[i], 0.f);
            else if (args.op == 2) v[i] = tanhf(v[i]);
        }
        size_t base = (size_t)(bM + row) * args.ldc + bN + col;
        if (args.Cf)
            *reinterpret_cast<float4*>(args.Cf + base) = make_float4(v[0], v[1], v[2], v[3]);
        if (args.Ch) {
            uint32_t hp[2], lp[2];
#pragma unroll
            for (int h = 0; h < 2; h++) {
                bf16 a = __float2bfloat16(v[2*h]);
                bf16 b = __float2bfloat16(v[2*h+1]);
                bf16 la = __float2bfloat16(v[2*h]   - __bfloat162float(a));
                bf16 lb = __float2bfloat16(v[2*h+1] - __bfloat162float(b));
                hp[h] = (uint32_t)__bfloat16_as_ushort(a) | ((uint32_t)__bfloat16_as_ushort(b) << 16);
                lp[h] = (uint32_t)__bfloat16_as_ushort(la) | ((uint32_t)__bfloat16_as_ushort(lb) << 16);
            }
            *reinterpret_cast<uint2*>(args.Ch + base) = make_uint2(hp[0], hp[1]);
            *reinterpret_cast<uint2*>(args.Cl + base) = make_uint2(lp[0], lp[1]);
        }
    }
    __syncthreads();
    if (wid == 0) { tc_relinq(); tc_dealloc(tmem, 128); }

#else
    // ======================= HMMA mma.sync path (plain sm_103) ===========
    // 3-stage cp.async pipeline, ONE __syncthreads per 32-wide K chunk.
    int segBase[7];
    segBase[0] = 0;
#pragma unroll
    for (int i = 0; i < 6; i++)
        segBase[i + 1] = segBase[i] + ((i < args.nseg) ? (args.s[i].K >> 5) : 0);
    const int nch = segBase[6];

    const int wm = (wid >> 1) * 32;
    const int wn = (wid & 1) * 64;

    float ac[2][8][4];
#pragma unroll
    for (int mt = 0; mt < 2; mt++)
#pragma unroll
        for (int nt = 0; nt < 8; nt++)
#pragma unroll
            for (int i = 0; i < 4; i++) ac[mt][nt][i] = 0.f;

    auto slotOf = [&](int cc) -> uint32_t {
        int s3 = cc % 3;
        return sb + (uint32_t)s3 * 20480u;
    };
    auto loadChunk = [&](int cc) {
        int s = 0;
#pragma unroll
        for (int i = 0; i < 5; i++) if (cc >= segBase[i + 1]) s = i + 1;
        const bf16* A = args.s[s].A;
        const bf16* B = args.s[s].B;
        const int K = args.s[s].K;
        const int k0 = (cc - segBase[s]) * 32;
        uint32_t st = slotOf(cc);
#pragma unroll
        for (int i = 0; i < 2; i++) {
            int ch = tid + i * 256;
            int row = ch >> 2, cb = ch & 3;
            cpa16(st + (uint32_t)(row * 80 + cb * 16),
                  A + (size_t)(bM + row) * K + k0 + cb * 8);
        }
#pragma unroll
        for (int i = 0; i < 2; i++) {
            int ch = tid + i * 256;
            int row = ch >> 2, cb = ch & 3;
            cpa16(st + 10240u + (uint32_t)(row * 80 + cb * 16),
                  B + (size_t)(bN + row) * K + k0 + cb * 8);
        }
    };

    loadChunk(0); cp_commit();
    if (nch > 1) { loadChunk(1); cp_commit(); }
    for (int cc = 0; cc < nch; cc++) {
        if (cc < nch - 1) cp_wait1(); else cp_wait0();
        __syncthreads();
        if (cc + 2 < nch) { loadChunk(cc + 2); cp_commit(); }
        uint32_t stA = slotOf(cc);
        uint32_t stB = stA + 10240u;
#pragma unroll
        for (int kk = 0; kk < 32; kk += 16) {
            uint32_t af[2][4], bfr[4][4];
#pragma unroll
            for (int mt = 0; mt < 2; mt++)
                ldsm4(af[mt], stA + (uint32_t)((wm + mt * 16 + (lane & 15)) * 80
                                               + (kk + (lane >> 4) * 8) * 2));
#pragma unroll
            for (int p = 0; p < 4; p++)
                ldsm4(bfr[p], stB + (uint32_t)((wn + p * 16 + (lane & 7) + ((lane >> 4) & 1) * 8) * 80
                                               + (kk + ((lane >> 3) & 1) * 8) * 2));
#pragma unroll
            for (int mt = 0; mt < 2; mt++)
#pragma unroll
                for (int nt = 0; nt < 8; nt++)
                    mma16816(ac[mt][nt], af[mt], &bfr[nt >> 1][(nt & 1) * 2]);
        }
    }

    if (args.op == 3) {
        // fused LSTM cell: interleaved gate columns 4h+{i,f,g,o}
#pragma unroll
        for (int mt = 0; mt < 2; mt++)
#pragma unroll
            for (int nt = 0; nt < 8; nt++) {
                int row = bM + wm + mt * 16 + (lane >> 2);
                int col = bN + wn + nt * 8 + 2 * (lane & 3);
                float v0 = ac[mt][nt][0] + args.bias1[col];
                float v1 = ac[mt][nt][1] + args.bias1[col + 1];
                float v2 = ac[mt][nt][2] + args.bias1[col];
                float v3 = ac[mt][nt][3] + args.bias1[col + 1];
                float p0 = __shfl_xor_sync(0xffffffffu, v0, 1);
                float p1 = __shfl_xor_sync(0xffffffffu, v1, 1);
                float p2 = __shfl_xor_sync(0xffffffffu, v2, 1);
                float p3 = __shfl_xor_sync(0xffffffffu, v3, 1);
                if (!(lane & 1)) {
                    int h = col >> 2;
                    float c1 = args.c0[(size_t)row * HDIM + h];
                    float c2 = args.c0[(size_t)(row + 8) * HDIM + h];
                    float cc1 = sigf(v1) * c1 + sigf(v0) * tanhf(p0);
                    float x1 = sigf(p1) * tanhf(cc1);
                    float cc2 = sigf(v3) * c2 + sigf(v2) * tanhf(p2);
                    float x2 = sigf(p3) * tanhf(cc2);
                    bf16 h1 = __float2bfloat16(x1);
                    bf16 h2 = __float2bfloat16(x2);
                    size_t i1 = (size_t)row * HDIM + h;
                    size_t i2 = (size_t)(row + 8) * HDIM + h;
                    args.Ch[i1] = h1;
                    args.Cl[i1] = __float2bfloat16(x1 - __bfloat162float(h1));
                    args.Ch[i2] = h2;
                    args.Cl[i2] = __float2bfloat16(x2 - __bfloat162float(h2));
                    if (args.tso) { args.tso[i1] = x1; args.tso[i2] = x2; }
                }
            }
        return;
    }

    auto storePair = [&](int row, int col, float v0, float v1) {
        if (args.bias1) { v0 += args.bias1[col]; v1 += args.bias1[col + 1]; }
        if (args.bias2) { v0 += args.bias2[col]; v1 += args.bias2[col + 1]; }
        if (args.op == 1)      { v0 = fmaxf(v0, 0.f); v1 = fmaxf(v1, 0.f); }
        else if (args.op == 2) { v0 = tanhf(v0); v1 = tanhf(v1); }
        size_t base = (size_t)row * args.ldc + col;
        if (args.Cf)
            *reinterpret_cast<float2*>(args.Cf + base) = make_float2(v0, v1);
        if (args.Ch) {
            bf16 h0 = __float2bfloat16(v0), h1 = __float2bfloat16(v1);
            bf16 l0 = __float2bfloat16(v0 - __bfloat162float(h0));
            bf16 l1 = __float2bfloat16(v1 - __bfloat162float(h1));
            *reinterpret_cast<uint32_t*>(args.Ch + base) =
                (uint32_t)__bfloat16_as_ushort(h0) | ((uint32_t)__bfloat16_as_ushort(h1) << 16);
            *reinterpret_cast<uint32_t*>(args.Cl + base) =
                (uint32_t)__bfloat16_as_ushort(l0) | ((uint32_t)__bfloat16_as_ushort(l1) << 16);
        }
    };
#pragma unroll
    for (int mt = 0; mt < 2; mt++)
#pragma unroll
        for (int nt = 0; nt < 8; nt++) {
            int row = bM + wm + mt * 16 + (lane >> 2);
            int col = bN + wn + nt * 8 + 2 * (lane & 3);
            storePair(row,     col, ac[mt][nt][0], ac[mt][nt][1]);
            storePair(row + 8, col, ac[mt][nt][2], ac[mt][nt][3]);
        }
#endif
}

// ============================ conversion ============================
// permBlock>0: within each permBlock-row block, dst row r maps to src row (r&3)*512 + (r>>2)
__global__ void conv_hl(const float* __restrict__ src, int rows, int Ks, int ld, int Kd,
                        bf16* __restrict__ h, bf16* __restrict__ l,
                        const float* __restrict__ divr, int permBlock)
{
    int idx = blockIdx.x * blockDim.x + threadIdx.x;
    if (idx >= rows * Kd) return;
    int r = idx / Kd, k = idx - r * Kd;
    int sr = r;
    if (permBlock) {
        int blk = r / permBlock, rr = r - blk * permBlock;
        sr = blk * permBlock + (rr & 3) * 512 + (rr >> 2);
    }
    float v = (k < Ks) ? src[(size_t)sr * ld + k] : 0.f;
    if (divr) v /= divr[r];
    bf16 hb = __float2bfloat16(v);
    h[idx] = hb;
    l[idx] = __float2bfloat16(v - __bfloat162float(hb));
}

// permuted combined bias: biasp[l][4h+g] = b_ih[l][g*512+h] + b_hh[l][g*512+h]
__global__ void biasp_kernel(const float* __restrict__ b_ih, const float* __restrict__ b_hh,
                             float* __restrict__ bp)
{
    int idx = blockIdx.x * blockDim.x + threadIdx.x;
    if (idx >= NL * G4) return;
    int l = idx >> 11, rr = idx & 2047;
    int sr = (rr & 3) * 512 + (rr >> 2);
    bp[idx] = b_ih[l * G4 + sr] + b_hh[l * G4 + sr];
}

__global__ void raw_dnn_kernel(const float* __restrict__ z, const float* __restrict__ W2,
                               const float* __restrict__ b2, const float* __restrict__ rng,
                               const void* __restrict__ scale_ptr,
                               float* __restrict__ raw_out, float* __restrict__ dnn_out)
{
    __shared__ float zs[2 * HDIM];
    int b = blockIdx.x;
    const float* zr = z + (size_t)b * 2 * HDIM;
    for (int i = threadIdx.x; i < 2 * HDIM; i += blockDim.x) zs[i] = zr[i];
    __syncthreads();
    int warp = threadIdx.x >> 5, lane = threadIdx.x & 31;
    int bits = *(const int*)scale_ptr;
    float f = __int_as_float(bits);
    float af = fabsf(f);
    float s = (af >= 1e-30f && af <= 1e30f) ? f : (float)bits;
    for (int o = warp; o < OUTD; o += 8) {
        const float* w = W2 + (size_t)o * 2 * HDIM;
        float acc = 0.f;
        for (int k = lane; k < 2 * HDIM; k += 32) acc += zs[k] * w[k];
#pragma unroll
        for (int off = 16; off; off >>= 1) acc += __shfl_xor_sync(0xffffffffu, acc, off);
        if (lane == 0) {
            float r = acc + b2[o];
            raw_out[(size_t)b * OUTD + o] = r;
            dnn_out[(size_t)b * OUTD + o] = (1.f / (1.f + expf(-r * s))) * rng[o];
        }
    }
}

// ============================ ODE ============================
#define LN2D 0.6931471805599453
#define C_RI  ((float)(LN2D / 5.0))
#define C_RD  ((float)(LN2D / 2.0))
#define C_RRI ((float)(LN2D / 10.0))
#define C_RRH ((float)(LN2D / 15.0))
#define C_RRV ((float)(LN2D / 10.0))
#define TWO_OVER_PI 0.6366197723675814f
#define HALF_PI     1.5707963267948966f

__device__ __forceinline__ void covid_deriv(const float y[16], float gam, float pdt,
                                            float aN, float r_dth, float d[16])
{
    float S = y[0], E = y[1], I = y[2];
    float AR = y[3], DHR = y[4], DQR = y[5], AD = y[6], DHD = y[7], DQD = y[8];
    float DVR = y[12], DVD = y[13];
    float inf = aN * gam * S * I;
    float det = C_RD * I;
    float d1m = det * (1.f - pdt);
    float dp  = det * pdt;
    d[0] = -inf;
    d[1] = inf - C_RI * E;
    d[2] = C_RI * E - det;
    d[3] = d1m * 0.8f - C_RRI * AR;
    d[4] = d1m * 0.03f - C_RRH * DHR;
    d[5] = d1m * 0.17f - C_RRI * DQR;
    d[6] = dp * 0.8f - r_dth * AD;
    d[7] = dp * 0.03f - r_dth * DHD;
    d[8] = dp * 0.17f - r_dth * DQD;
    d[9] = C_RRI * (AR + DQR) + C_RRH * DHR;
    d[10] = r_dth * (AD + DQD + DHD);
    d[11] = det * 0.03f;
    d[12] = d1m * 0.0075f - C_RRV * DVR;
    d[13] = dp * 0.0075f - r_dth * DVD;
    d[14] = r_dth * (DHD + DQD);
    d[15] = det * 0.2f;
}
__device__ __forceinline__ float gam_f(float t, float days, float rs20,
                                       float jump, float t_jump, float inv2s2)
{
    float dtj = t - t_jump;
    return TWO_OVER_PI * atanf((days - t) * rs20) + 1.0f + jump * __expf(-dtj * dtj * inv2s2);
}
__device__ __forceinline__ float pdt_f(float t, float pc, float rdd20)
{
    return pc * (atanf(-t * rdd20) + HALF_PI) + 0.001f;
}

__global__ void ode_kernel(const float* __restrict__ pop, const float* __restrict__ ccn,
                           const float* __restrict__ mort, const float* __restrict__ dnn,
                           float* __restrict__ sol)
{
    int b = blockIdx.x * blockDim.x + threadIdx.x;
    if (b >= BATCH) return;
    const float* dn = dnn + (size_t)b * OUTD;
    float alpha = dn[11], days = dn[12], r_s = dn[13], r_dth = dn[14], p_dth = dn[15];
    float r_dthdecay = dn[16], k1 = dn[17], k2 = dn[18], jump = dn[19];
    float t_jump = dn[20], stdn = dn[21];

    float N = pop[b];
    float PopI = ccn[b];
    float PopD = floorf(mort[b] * PopI);
    float R0 = (PopI - PopD > 5.0f * PopD) ? 5.0f * PopD : 0.0f;
    float PopCI = PopI - PopD - R0;
    float ciPD = PopCI / 0.2f;
    float omp = 1.0f - p_dth;

    float y[16];
    y[0] = N - ciPD * (k1 + k2) - R0 / 0.2f - PopD / 0.2f;
    y[1] = ciPD * k1;  y[2] = ciPD * k2;
    y[3] = (ciPD - PopCI) * omp;
    y[4] = PopCI * 0.15f * omp;
    y[5] = PopCI * 0.85f * omp;
    y[6] = (ciPD - PopCI) * p_dth;
    y[7] = PopCI * 0.15f * p_dth;
    y[8] = PopCI * 0.85f * p_dth;
    y[9] = R0 / 0.2f;  y[10] = PopD / 0.2f;
    y[11] = PopCI * 0.15f;
    y[12] = PopCI * 0.0375f * omp;
    y[13] = PopCI * 0.0375f * p_dth;
    y[14] = PopD;  y[15] = PopI;

    float* srow = sol + (size_t)b * TPTS * 16;
#pragma unroll
    for (int i = 0; i < 16; i++) srow[i] = y[i];

    float aN = alpha / N;
    float rs20 = r_s * 0.05f;
    float rdd20 = r_dthdecay * 0.05f;
    float inv2s2 = 1.0f / (2.0f * stdn * stdn);
    float pc = TWO_OVER_PI * (p_dth - 0.001f);

    for (int seg = 0; seg < TPTS - 1; seg++) {
        float t0 = (float)seg;
        for (int j = 0; j < 10; j++) {
            float t = t0 + (float)j * 0.1f;
            float g1 = gam_f(t, days, rs20, jump, t_jump, inv2s2);
            float g2 = gam_f(t + 0.05f, days, rs20, jump, t_jump, inv2s2);
            float g3 = gam_f(t + 0.1f, days, rs20, jump, t_jump, inv2s2);
            float p1 = pdt_f(t, pc, rdd20);
            float p2 = pdt_f(t + 0.05f, pc, rdd20);
            float p3 = pdt_f(t + 0.1f, pc, rdd20);
            float k[16], acc[16], yy[16];
            covid_deriv(y, g1, p1, aN, r_dth, k);
#pragma unroll
            for (int i = 0; i < 16; i++) { acc[i] = k[i]; yy[i] = y[i] + 0.05f * k[i]; }
            covid_deriv(yy, g2, p2, aN, r_dth, k);
#pragma unroll
            for (int i = 0; i < 16; i++) { acc[i] += 2.f * k[i]; yy[i] = y[i] + 0.05f * k[i]; }
            covid_deriv(yy, g2, p2, aN, r_dth, k);
#pragma unroll
            for (int i = 0; i < 16; i++) { acc[i] += 2.f * k[i]; yy[i] = y[i] + 0.1f * k[i]; }
            covid_deriv(yy, g3, p3, aN, r_dth, k);
#pragma unroll
            for (int i = 0; i < 16; i++) y[i] += (0.1f / 6.0f) * (acc[i] + k[i]);
        }
        float* o = srow + (size_t)(seg + 1) * 16;
#pragma unroll
        for (int i = 0; i < 16; i++) o[i] = y[i];
    }
}

// ============================ launch ============================
static void* sym(const void* s) { void* p; cudaGetSymbolAddress(&p, s); return p; }

extern "C" void kernel_launch(void* const* d_in, const int* in_sizes, int n_in,
                              void* d_out, int out_size)
{
    const float* mi    = (const float*)d_in[0];
    const float* pop   = (const float*)d_in[1];
    const float* ccn   = (const float*)d_in[2];
    const float* mort  = (const float*)d_in[3];
    const float* h0    = (const float*)d_in[4];
    const float* c0    = (const float*)d_in[5];
    const float* W_ih0 = (const float*)d_in[6];
    const float* W_ihR = (const float*)d_in[7];
    const float* W_hh  = (const float*)d_in[8];
    const float* b_ih  = (const float*)d_in[9];
    const float* b_hh  = (const float*)d_in[10];
    const float* mW1   = (const float*)d_in[11];
    const float* mb1   = (const float*)d_in[12];
    const float* mW2   = (const float*)d_in[13];
    const float* mb2   = (const float*)d_in[14];
    const float* rW1   = (const float*)d_in[15];
    const float* rb1   = (const float*)d_in[16];
    const float* rW2   = (const float*)d_in[17];
    const float* rb2   = (const float*)d_in[18];
    const float* rng   = (const float*)d_in[19];
    const void*  scl   = d_in[20];

    float* out = (float*)d_out;
    float* sol = out;
    float* dnn = out + (size_t)BATCH * TPTS * 16;
    float* ts  = dnn + (size_t)BATCH * OUTD;
    float* raw = ts  + (size_t)BATCH * HDIM;

    float* zb    = (float*)sym(g_z);
    float* biasp = (float*)sym(g_biasp);
    bf16 *x30h = (bf16*)sym(g_x30h), *x30l = (bf16*)sym(g_x30l);
    bf16 *mih  = (bf16*)sym(g_mih),  *mil  = (bf16*)sym(g_mil);
    bf16 *wi0h = (bf16*)sym(g_wi0h), *wi0l = (bf16*)sym(g_wi0l);
    bf16 *wirh = (bf16*)sym(g_wirh), *wirl = (bf16*)sym(g_wirl);
    bf16 *whhh = (bf16*)sym(g_whhh), *whhl = (bf16*)sym(g_whhl);
    bf16 *h0h  = (bf16*)sym(g_h0h),  *h0l  = (bf16*)sym(g_h0l);
    bf16 *mw1h = (bf16*)sym(g_mw1h), *mw1l = (bf16*)sym(g_mw1l);
    bf16 *mw2h = (bf16*)sym(g_mw2h), *mw2l = (bf16*)sym(g_mw2l);
    bf16 *r1ah = (bf16*)sym(g_r1ah), *r1al = (bf16*)sym(g_r1al);
    bf16 *r1bh = (bf16*)sym(g_r1bh), *r1bl = (bf16*)sym(g_r1bl);
    bf16 *xAh  = (bf16*)sym(g_xAh),  *xAl  = (bf16*)sym(g_xAl);
    bf16 *xBh  = (bf16*)sym(g_xBh),  *xBl  = (bf16*)sym(g_xBl);
    bf16 *m1h  = (bf16*)sym(g_m1h),  *m1l  = (bf16*)sym(g_m1l);
    bf16 *m2h  = (bf16*)sym(g_m2h),  *m2l  = (bf16*)sym(g_m2l);

    static cudaStream_t s1 = nullptr;
    static cudaEvent_t  evF = nullptr, evJ = nullptr, evC = nullptr;
    if (!s1) {
        cudaStreamCreateWithFlags(&s1, cudaStreamNonBlocking);
        cudaEventCreateWithFlags(&evF, cudaEventDisableTiming);
        cudaEventCreateWithFlags(&evJ, cudaEventDisableTiming);
        cudaEventCreateWithFlags(&evC, cudaEventDisableTiming);
        cudaFuncSetAttribute(gemm_tc, cudaFuncAttributeMaxDynamicSharedMemorySize, GEMM_SMEM);
    }

    auto CV = [&](cudaStream_t st, const float* s, int rows, int Ks, int ld, int Kd,
                  bf16* h, bf16* l, const float* dv, int perm) {
        int n = rows * Kd;
        conv_hl<<<(n + 255) / 256, 256, 0, st>>>(s, rows, Ks, ld, Kd, h, l, dv, perm);
    };
    auto GL = [&](cudaStream_t st, dim3 grid, Seg* sg, int ns, const float* b1, const float* b2,
                  const float* c0p, float* tso,
                  float* Cf, bf16* Ch, bf16* Cl, int ldc, int op) {
        GArgs a = {};
        for (int i = 0; i < ns; i++) a.s[i] = sg[i];
        a.nseg = ns; a.bias1 = b1; a.bias2 = b2; a.c0 = c0p; a.tso = tso;
        a.Cf = Cf; a.Ch = Ch; a.Cl = Cl; a.ldc = ldc; a.op = op;
        gemm_tc<<<grid, 256, GEMM_SMEM, st>>>(a);
    };

    // fork s1 from capture origin
    cudaEventRecord(evF, 0);
    cudaStreamWaitEvent(s1, evF, 0);

    // ---- default stream: ONLY layer-0-critical conversions ----
    CV(0, mi,    BATCH, TTL,  IN_DIM, 64,   x30h, x30l, pop,     0);
    CV(0, W_ih0, G4,    TTL,  TTL,    64,   wi0h, wi0l, nullptr, 2048);
    CV(0, W_hh,  G4,    HDIM, HDIM,   HDIM, whhh, whhl, nullptr, 2048);  // layer 0 only
    CV(0, h0,    BATCH, HDIM, HDIM,   HDIM, h0h,  h0l,  nullptr, 0);     // layer 0 only
    biasp_kernel<<<(NL * G4 + 255) / 256, 256>>>(b_ih, b_hh, biasp);

    // ---- s1: conversions for layers 1-4, then meta branch + readout weights ----
    CV(s1, W_ihR,                        4 * G4,    HDIM, HDIM,   HDIM, wirh, wirl, nullptr, 2048);
    CV(s1, W_hh + (size_t)G4 * HDIM,     4 * G4,    HDIM, HDIM,   HDIM,
       whhh + (size_t)G4 * HDIM, whhl + (size_t)G4 * HDIM, nullptr, 2048);
    CV(s1, h0 + (size_t)BATCH * HDIM,    4 * BATCH, HDIM, HDIM,   HDIM,
       h0h + (size_t)BATCH * HDIM, h0l + (size_t)BATCH * HDIM, nullptr, 0);
    cudaEventRecord(evC, s1);   // LSTM layers 1-4 depend on this

    CV(s1, mi + TTL,   BATCH,    30,   IN_DIM, 64,   mih,  mil,  nullptr, 0);
    CV(s1, mW1,        HDIM,     30,   30,     64,   mw1h, mw1l, nullptr, 0);
    CV(s1, mW2,        HDIM,     HDIM, HDIM,   HDIM, mw2h, mw2l, nullptr, 0);
    CV(s1, rW1,        2 * HDIM, HDIM, 2*HDIM, HDIM, r1ah, r1al, nullptr, 0);
    CV(s1, rW1 + HDIM, 2 * HDIM, HDIM, 2*HDIM, HDIM, r1bh, r1bl, nullptr, 0);
    dim3 mGrid(HDIM / 128, BATCH / 128);
    { Seg sg[3] = { {mih, mw1h, 64}, {mil, mw1h, 64}, {mih, mw1l, 64} };
      GL(s1, mGrid, sg, 3, mb1, nullptr, nullptr, nullptr, nullptr, m1h, m1l, HDIM, 1); }
    { Seg sg[3] = { {m1h, mw2h, HDIM}, {m1l, mw2h, HDIM}, {m1h, mw2l, HDIM} };
      GL(s1, mGrid, sg, 3, mb2, nullptr, nullptr, nullptr, nullptr, m2h, m2l, HDIM, 1); }
    cudaEventRecord(evJ, s1);

    // ---- default stream: LSTM chain, fused cell epilogue, ping-pong x ----
    dim3 gGrid(G4 / 128, BATCH / 128);
    for (int l = 0; l < NL; l++) {
        if (l == 1) cudaStreamWaitEvent(0, evC, 0);   // layers 1-4 weight conversions ready
        bf16* ah = (l == 0) ? x30h : ((l & 1) ? xAh : xBh);
        bf16* al = (l == 0) ? x30l : ((l & 1) ? xAl : xBl);
        bf16* oh = (l & 1) ? xBh : xAh;   // write the OTHER buffer
        bf16* ol = (l & 1) ? xBl : xAl;
        int   Kx = l ? HDIM : 64;
        bf16* wh = l ? (wirh + (size_t)(l - 1) * G4 * HDIM) : wi0h;
        bf16* wl = l ? (wirl + (size_t)(l - 1) * G4 * HDIM) : wi0l;
        bf16* hh = h0h + (size_t)l * BATCH * HDIM;
        bf16* hl = h0l + (size_t)l * BATCH * HDIM;
        bf16* Wh = whhh + (size_t)l * G4 * HDIM;
        bf16* Wl = whhl + (size_t)l * G4 * HDIM;
        Seg sg[6] = { {ah, wh, Kx}, {al, wh, Kx}, {ah, wl, Kx},
                      {hh, Wh, HDIM}, {hl, Wh, HDIM}, {hh, Wl, HDIM} };
        GL(0, gGrid, sg, 6, biasp + (size_t)l * G4, nullptr,
           c0 + (size_t)l * BATCH * HDIM, (l == NL - 1) ? ts : nullptr,
           nullptr, oh, ol, HDIM, 3);
    }
    // layer 4 (l=4, even) wrote buffer A
    bf16* xfh = xAh;
    bf16* xfl = xAl;

    // join meta branch, then readout
    cudaStreamWaitEvent(0, evJ, 0);
    dim3 zGrid(2 * HDIM / 128, BATCH / 128);
    { Seg sg[6] = { {xfh, r1ah, HDIM}, {xfl, r1ah, HDIM}, {xfh, r1al, HDIM},
                    {m2h, r1bh, HDIM}, {m2l, r1bh, HDIM}, {m2h, r1bl, HDIM} };
      GL(0, zGrid, sg, 6, rb1, nullptr, nullptr, nullptr, zb, nullptr, nullptr, 2 * HDIM, 2); }

    raw_dnn_kernel<<<BATCH, 256>>>(zb, rW2, rb2, rng, scl, raw, dnn);
    ode_kernel<<<(BATCH + 63) / 64, 64>>>(pop, ccn, mort, dnn, sol);
}